// round 1
// baseline (speedup 1.0000x reference)
#include <cuda_runtime.h>
#include <cuda_bf16.h>
#include <math.h>

// Problem constants
#define B_   4
#define T_   2048
#define D_   1024
#define H_   16
#define HD_  64
#define NTOK (B_ * T_)   // 8192

// ---------------------------------------------------------------------------
// Scratch (device globals: allocation-free rule)
// ---------------------------------------------------------------------------
__device__ float g_q[NTOK * D_];
__device__ float g_k[NTOK * D_];
__device__ float g_v[NTOK * D_];
__device__ float g_o[NTOK * D_];
__device__ float g_cos[T_ * 32];
__device__ float g_sin[T_ * 32];

// ---------------------------------------------------------------------------
// RoPE tables, computed in fp64 (fast-math cosf is unsafe at theta ~ 2048 rad).
// Mimics reference rounding: freq rounded to fp32, theta = fp32(t * freq),
// then correctly-rounded cos/sin of that fp32 theta.
// ---------------------------------------------------------------------------
__global__ void rope_tables_kernel() {
    int i = blockIdx.x * blockDim.x + threadIdx.x;
    if (i >= T_ * 32) return;
    int t = i >> 5;
    int j = i & 31;
    float f32 = 0.0f;
    if (j < 16) f32 = (float)pow(1.0 / 1024.0, (double)j / 15.0);
    float theta = (float)t * f32;
    g_cos[i] = (float)cos((double)theta);
    g_sin[i] = (float)sin((double)theta);
}

// ---------------------------------------------------------------------------
// GEMM: C[M,N] = A[M,K] @ B[N,K]^T   (both row-major, K contiguous — "NT")
// 128x128 block tile, BK=16, 256 threads, 8x8 microtile.
// M, N, K all multiples of 128 here: no bounds checks.
// ---------------------------------------------------------------------------
#define GBK 16

__global__ __launch_bounds__(256) void gemm_nt_kernel(
    const float* __restrict__ A, const float* __restrict__ Bm,
    float* __restrict__ C, int M, int N, int K)
{
    __shared__ float As[GBK][132];   // As[k][m], padded
    __shared__ float Bs[GBK][132];   // Bs[k][n], padded

    int tid = threadIdx.x;
    int bm = blockIdx.y * 128;
    int bn = blockIdx.x * 128;
    int ty = tid >> 4;       // 0..15
    int tx = tid & 15;       // 0..15

    float acc[8][8];
#pragma unroll
    for (int i = 0; i < 8; i++)
#pragma unroll
        for (int j = 0; j < 8; j++) acc[i][j] = 0.0f;

    int lrow = tid >> 2;           // 0..63
    int lk   = (tid & 3) << 2;     // 0,4,8,12
    const float* Ap = A  + (size_t)(bm + lrow) * K + lk;
    const float* Bp = Bm + (size_t)(bn + lrow) * K + lk;

    for (int k0 = 0; k0 < K; k0 += GBK) {
        float4 a0 = *(const float4*)(Ap + k0);
        float4 a1 = *(const float4*)(Ap + (size_t)64 * K + k0);
        float4 b0 = *(const float4*)(Bp + k0);
        float4 b1 = *(const float4*)(Bp + (size_t)64 * K + k0);

        As[lk + 0][lrow] = a0.x; As[lk + 1][lrow] = a0.y;
        As[lk + 2][lrow] = a0.z; As[lk + 3][lrow] = a0.w;
        As[lk + 0][lrow + 64] = a1.x; As[lk + 1][lrow + 64] = a1.y;
        As[lk + 2][lrow + 64] = a1.z; As[lk + 3][lrow + 64] = a1.w;

        Bs[lk + 0][lrow] = b0.x; Bs[lk + 1][lrow] = b0.y;
        Bs[lk + 2][lrow] = b0.z; Bs[lk + 3][lrow] = b0.w;
        Bs[lk + 0][lrow + 64] = b1.x; Bs[lk + 1][lrow + 64] = b1.y;
        Bs[lk + 2][lrow + 64] = b1.z; Bs[lk + 3][lrow + 64] = b1.w;

        __syncthreads();

#pragma unroll
        for (int kk = 0; kk < GBK; kk++) {
            float4 av0 = *(const float4*)&As[kk][ty << 2];
            float4 av1 = *(const float4*)&As[kk][(ty << 2) + 64];
            float4 bv0 = *(const float4*)&Bs[kk][tx << 2];
            float4 bv1 = *(const float4*)&Bs[kk][(tx << 2) + 64];
            float a[8] = {av0.x, av0.y, av0.z, av0.w, av1.x, av1.y, av1.z, av1.w};
            float b[8] = {bv0.x, bv0.y, bv0.z, bv0.w, bv1.x, bv1.y, bv1.z, bv1.w};
#pragma unroll
            for (int i = 0; i < 8; i++)
#pragma unroll
                for (int j = 0; j < 8; j++)
                    acc[i][j] = fmaf(a[i], b[j], acc[i][j]);
        }
        __syncthreads();
    }

#pragma unroll
    for (int i = 0; i < 8; i++) {
        int row = bm + ((i < 4) ? ((ty << 2) + i) : (64 + (ty << 2) + i - 4));
        float4 c0 = make_float4(acc[i][0], acc[i][1], acc[i][2], acc[i][3]);
        float4 c1 = make_float4(acc[i][4], acc[i][5], acc[i][6], acc[i][7]);
        *(float4*)&C[(size_t)row * N + bn + (tx << 2)]      = c0;
        *(float4*)&C[(size_t)row * N + bn + 64 + (tx << 2)] = c1;
    }
}

// ---------------------------------------------------------------------------
// Fused per-head RMSNorm + RoPE for Q and K (in place).
// One warp per (token, head). Lane l handles the rotary pair (l, l+32).
// ---------------------------------------------------------------------------
__global__ __launch_bounds__(256) void norm_rope_kernel() {
    int gw   = (blockIdx.x * blockDim.x + threadIdx.x) >> 5;
    int lane = threadIdx.x & 31;
    if (gw >= NTOK * H_) return;

    int token = gw >> 4;          // / H_
    int t = token & (T_ - 1);     // token % T_
    size_t base = (size_t)gw * 64;

    float c = g_cos[t * 32 + lane];
    float s = g_sin[t * 32 + lane];

    {   // Q
        float a  = g_q[base + lane];
        float b2 = g_q[base + lane + 32];
        float ss = a * a + b2 * b2;
#pragma unroll
        for (int m = 16; m > 0; m >>= 1) ss += __shfl_xor_sync(0xffffffffu, ss, m);
        float r = rsqrtf(ss * (1.0f / 64.0f) + 1e-6f);
        a *= r; b2 *= r;
        g_q[base + lane]      = a * c + b2 * s;
        g_q[base + lane + 32] = -a * s + b2 * c;
    }
    {   // K
        float a  = g_k[base + lane];
        float b2 = g_k[base + lane + 32];
        float ss = a * a + b2 * b2;
#pragma unroll
        for (int m = 16; m > 0; m >>= 1) ss += __shfl_xor_sync(0xffffffffu, ss, m);
        float r = rsqrtf(ss * (1.0f / 64.0f) + 1e-6f);
        a *= r; b2 *= r;
        g_k[base + lane]      = a * c + b2 * s;
        g_k[base + lane + 32] = -a * s + b2 * c;
    }
}

// ---------------------------------------------------------------------------
// Flash attention (causal), fp32. Block handles (bh, 64-query tile).
// BN=64 key tile. 256 threads = 16x16, 4x4 microtile. Online softmax.
// ---------------------------------------------------------------------------
#define FPAD 68
#define FLASH_SMEM (4 * 64 * FPAD * 4)

__global__ __launch_bounds__(256) void flash_kernel(
    const float* __restrict__ Q, const float* __restrict__ K,
    const float* __restrict__ V, float* __restrict__ O)
{
    extern __shared__ float sm[];
    float* Qs  = sm;                 // [64 rows][FPAD] : Qs[row][hd]
    float* KsT = sm + 64 * FPAD;     // [64 hd][FPAD]   : KsT[hd][key]
    float* Vs  = KsT + 64 * FPAD;    // [64 key][FPAD]  : Vs[key][hd]
    float* Ps  = Vs + 64 * FPAD;     // [64 row][FPAD]  : Ps[row][key]

    int qt = gridDim.x - 1 - blockIdx.x;   // big tiles first
    int bh = blockIdx.y;
    int b = bh >> 4, h = bh & 15;

    int tid = threadIdx.x;
    int ty = tid >> 4, tx = tid & 15;
    int ri = ty << 2;

    // Load Q tile (scaled by 1/sqrt(HD) = 0.125)
#pragma unroll
    for (int r = 0; r < 4; r++) {
        int row = (tid >> 4) + r * 16;
        int hd4 = (tid & 15) << 2;
        int t = qt * 64 + row;
        size_t gi = ((((size_t)b * T_ + t) * H_ + h) << 6) + hd4;
        float4 qv = *(const float4*)&Q[gi];
        *(float4*)&Qs[row * FPAD + hd4] =
            make_float4(qv.x * 0.125f, qv.y * 0.125f, qv.z * 0.125f, qv.w * 0.125f);
    }

    float m[4], l[4], acc[4][4];
#pragma unroll
    for (int i = 0; i < 4; i++) {
        m[i] = -1e30f; l[i] = 0.0f;
#pragma unroll
        for (int j = 0; j < 4; j++) acc[i][j] = 0.0f;
    }

    for (int jt = 0; jt <= qt; jt++) {
        __syncthreads();   // protect prev-iter reads of KsT/Vs/Ps, publish Qs on iter 0

        // Load K (transposed) and V tiles
#pragma unroll
        for (int r = 0; r < 4; r++) {
            int key = (tid >> 4) + r * 16;
            int hd4 = (tid & 15) << 2;
            int t = jt * 64 + key;
            size_t gi = ((((size_t)b * T_ + t) * H_ + h) << 6) + hd4;
            float4 kv = *(const float4*)&K[gi];
            KsT[(hd4 + 0) * FPAD + key] = kv.x;
            KsT[(hd4 + 1) * FPAD + key] = kv.y;
            KsT[(hd4 + 2) * FPAD + key] = kv.z;
            KsT[(hd4 + 3) * FPAD + key] = kv.w;
            float4 vv = *(const float4*)&V[gi];
            *(float4*)&Vs[key * FPAD + hd4] = vv;
        }
        __syncthreads();

        // S = Q @ K^T (already scaled)
        float s[4][4];
#pragma unroll
        for (int i = 0; i < 4; i++)
#pragma unroll
            for (int j = 0; j < 4; j++) s[i][j] = 0.0f;

#pragma unroll 8
        for (int kk = 0; kk < 64; kk++) {
            float q0 = Qs[(ri + 0) * FPAD + kk];
            float q1 = Qs[(ri + 1) * FPAD + kk];
            float q2 = Qs[(ri + 2) * FPAD + kk];
            float q3 = Qs[(ri + 3) * FPAD + kk];
            float4 k4 = *(const float4*)&KsT[kk * FPAD + (tx << 2)];
            s[0][0] = fmaf(q0, k4.x, s[0][0]); s[0][1] = fmaf(q0, k4.y, s[0][1]);
            s[0][2] = fmaf(q0, k4.z, s[0][2]); s[0][3] = fmaf(q0, k4.w, s[0][3]);
            s[1][0] = fmaf(q1, k4.x, s[1][0]); s[1][1] = fmaf(q1, k4.y, s[1][1]);
            s[1][2] = fmaf(q1, k4.z, s[1][2]); s[1][3] = fmaf(q1, k4.w, s[1][3]);
            s[2][0] = fmaf(q2, k4.x, s[2][0]); s[2][1] = fmaf(q2, k4.y, s[2][1]);
            s[2][2] = fmaf(q2, k4.z, s[2][2]); s[2][3] = fmaf(q2, k4.w, s[2][3]);
            s[3][0] = fmaf(q3, k4.x, s[3][0]); s[3][1] = fmaf(q3, k4.y, s[3][1]);
            s[3][2] = fmaf(q3, k4.z, s[3][2]); s[3][3] = fmaf(q3, k4.w, s[3][3]);
        }

        // Causal mask: only the diagonal tile needs it
        if (jt == qt) {
#pragma unroll
            for (int i = 0; i < 4; i++)
#pragma unroll
                for (int j = 0; j < 4; j++)
                    if ((tx << 2) + j > ri + i) s[i][j] = -1e30f;
        }

        // Online softmax update (row groups = 16 lanes sharing ty)
#pragma unroll
        for (int i = 0; i < 4; i++) {
            float mloc = fmaxf(fmaxf(s[i][0], s[i][1]), fmaxf(s[i][2], s[i][3]));
#pragma unroll
            for (int d = 8; d > 0; d >>= 1)
                mloc = fmaxf(mloc, __shfl_xor_sync(0xffffffffu, mloc, d));
            float mn = fmaxf(m[i], mloc);
            float alpha = __expf(m[i] - mn);
            float rs = 0.0f;
#pragma unroll
            for (int j = 0; j < 4; j++) {
                float p = __expf(s[i][j] - mn);
                s[i][j] = p;
                rs += p;
            }
#pragma unroll
            for (int d = 8; d > 0; d >>= 1)
                rs += __shfl_xor_sync(0xffffffffu, rs, d);
            l[i] = l[i] * alpha + rs;
            m[i] = mn;
#pragma unroll
            for (int j = 0; j < 4; j++) acc[i][j] *= alpha;
        }

        // Write P tile
#pragma unroll
        for (int i = 0; i < 4; i++)
            *(float4*)&Ps[(ri + i) * FPAD + (tx << 2)] =
                make_float4(s[i][0], s[i][1], s[i][2], s[i][3]);
        __syncthreads();

        // acc += P @ V
#pragma unroll 8
        for (int kk = 0; kk < 64; kk++) {
            float p0 = Ps[(ri + 0) * FPAD + kk];
            float p1 = Ps[(ri + 1) * FPAD + kk];
            float p2 = Ps[(ri + 2) * FPAD + kk];
            float p3 = Ps[(ri + 3) * FPAD + kk];
            float4 v4 = *(const float4*)&Vs[kk * FPAD + (tx << 2)];
            acc[0][0] = fmaf(p0, v4.x, acc[0][0]); acc[0][1] = fmaf(p0, v4.y, acc[0][1]);
            acc[0][2] = fmaf(p0, v4.z, acc[0][2]); acc[0][3] = fmaf(p0, v4.w, acc[0][3]);
            acc[1][0] = fmaf(p1, v4.x, acc[1][0]); acc[1][1] = fmaf(p1, v4.y, acc[1][1]);
            acc[1][2] = fmaf(p1, v4.z, acc[1][2]); acc[1][3] = fmaf(p1, v4.w, acc[1][3]);
            acc[2][0] = fmaf(p2, v4.x, acc[2][0]); acc[2][1] = fmaf(p2, v4.y, acc[2][1]);
            acc[2][2] = fmaf(p2, v4.z, acc[2][2]); acc[2][3] = fmaf(p2, v4.w, acc[2][3]);
            acc[3][0] = fmaf(p3, v4.x, acc[3][0]); acc[3][1] = fmaf(p3, v4.y, acc[3][1]);
            acc[3][2] = fmaf(p3, v4.z, acc[3][2]); acc[3][3] = fmaf(p3, v4.w, acc[3][3]);
        }
    }

    // Epilogue: normalize and write
#pragma unroll
    for (int i = 0; i < 4; i++) {
        float inv = 1.0f / l[i];
        int t = qt * 64 + ri + i;
        size_t gi = ((((size_t)b * T_ + t) * H_ + h) << 6) + (tx << 2);
        *(float4*)&O[gi] =
            make_float4(acc[i][0] * inv, acc[i][1] * inv, acc[i][2] * inv, acc[i][3] * inv);
    }
}

// ---------------------------------------------------------------------------
// Launch
// ---------------------------------------------------------------------------
extern "C" void kernel_launch(void* const* d_in, const int* in_sizes, int n_in,
                              void* d_out, int out_size)
{
    (void)in_sizes; (void)n_in; (void)out_size;
    const float* x  = (const float*)d_in[0];
    const float* wq = (const float*)d_in[1];
    const float* wk = (const float*)d_in[2];
    const float* wv = (const float*)d_in[3];
    const float* wo = (const float*)d_in[4];
    float* out = (float*)d_out;

    float *qp, *kp, *vp, *op;
    cudaGetSymbolAddress((void**)&qp, g_q);
    cudaGetSymbolAddress((void**)&kp, g_k);
    cudaGetSymbolAddress((void**)&vp, g_v);
    cudaGetSymbolAddress((void**)&op, g_o);

    rope_tables_kernel<<<(T_ * 32 + 255) / 256, 256>>>();

    dim3 gg(D_ / 128, NTOK / 128);
    gemm_nt_kernel<<<gg, 256>>>(x, wq, qp, NTOK, D_, D_);
    gemm_nt_kernel<<<gg, 256>>>(x, wk, kp, NTOK, D_, D_);
    gemm_nt_kernel<<<gg, 256>>>(x, wv, vp, NTOK, D_, D_);

    norm_rope_kernel<<<(NTOK * H_) / 8, 256>>>();

    cudaFuncSetAttribute(flash_kernel,
                         cudaFuncAttributeMaxDynamicSharedMemorySize, FLASH_SMEM);
    flash_kernel<<<dim3(T_ / 64, B_ * H_), 256, FLASH_SMEM>>>(qp, kp, vp, op);

    gemm_nt_kernel<<<gg, 256>>>(op, wo, out, NTOK, D_, D_);
}

// round 3
// speedup vs baseline: 1.3916x; 1.3916x over previous
#include <cuda_runtime.h>
#include <cuda_bf16.h>
#include <math.h>
#include <stdint.h>

// Problem constants
#define B_   4
#define T_   2048
#define D_   1024
#define H_   16
#define HD_  64
#define NTOK (B_ * T_)   // 8192

// ---------------------------------------------------------------------------
// Scratch (device globals: allocation-free rule)
// ---------------------------------------------------------------------------
__device__ float g_q[NTOK * D_];
__device__ float g_k[NTOK * D_];
__device__ float g_v[NTOK * D_];
__device__ float g_o[NTOK * D_];
__device__ float g_cos[T_ * 32];
__device__ float g_sin[T_ * 32];

// bf16 hi/lo splits (x / o share the same buffers; x is dead after q,k,v GEMMs)
__device__ __nv_bfloat16 g_ahi[NTOK * D_];
__device__ __nv_bfloat16 g_alo[NTOK * D_];
__device__ __nv_bfloat16 g_whi[4][D_ * D_];
__device__ __nv_bfloat16 g_wlo[4][D_ * D_];

// ---------------------------------------------------------------------------
// PTX helpers (base compute_103 target: mma.sync / ldmatrix / cp.async only)
// ---------------------------------------------------------------------------
__device__ __forceinline__ uint32_t smem_to_u32(const void* p) {
    uint32_t a;
    asm("{ .reg .u64 t; cvta.to.shared.u64 t, %1; cvt.u32.u64 %0, t; }"
        : "=r"(a) : "l"(p));
    return a;
}

__device__ __forceinline__ void ldsm_x4(uint32_t* r, uint32_t addr) {
    asm volatile("ldmatrix.sync.aligned.m8n8.x4.shared.b16 {%0,%1,%2,%3}, [%4];"
                 : "=r"(r[0]), "=r"(r[1]), "=r"(r[2]), "=r"(r[3]) : "r"(addr));
}

__device__ __forceinline__ void mma_bf16(float* c, const uint32_t* a, const uint32_t* b) {
    asm volatile(
        "mma.sync.aligned.m16n8k16.row.col.f32.bf16.bf16.f32 "
        "{%0,%1,%2,%3}, {%4,%5,%6,%7}, {%8,%9}, {%0,%1,%2,%3};"
        : "+f"(c[0]), "+f"(c[1]), "+f"(c[2]), "+f"(c[3])
        : "r"(a[0]), "r"(a[1]), "r"(a[2]), "r"(a[3]), "r"(b[0]), "r"(b[1]));
}

__device__ __forceinline__ void cp_async16(uint32_t dst, const void* src) {
    asm volatile("cp.async.cg.shared.global [%0], [%1], 16;"
                 :: "r"(dst), "l"(src));
}
__device__ __forceinline__ void cp_commit() {
    asm volatile("cp.async.commit_group;" ::: "memory");
}
template <int N>
__device__ __forceinline__ void cp_wait() {
    asm volatile("cp.async.wait_group %0;" :: "n"(N) : "memory");
}

// ---------------------------------------------------------------------------
// fp32 -> (bf16 hi, bf16 lo) split
// ---------------------------------------------------------------------------
__global__ __launch_bounds__(256) void split_kernel(
    const float* __restrict__ src, __nv_bfloat16* __restrict__ hi,
    __nv_bfloat16* __restrict__ lo, int n)
{
    int i4 = (blockIdx.x * blockDim.x + threadIdx.x) * 4;
    if (i4 >= n) return;
    float4 v = *(const float4*)(src + i4);
    __nv_bfloat16 h0 = __float2bfloat16(v.x);
    __nv_bfloat16 h1 = __float2bfloat16(v.y);
    __nv_bfloat16 h2 = __float2bfloat16(v.z);
    __nv_bfloat16 h3 = __float2bfloat16(v.w);
    __nv_bfloat16 l0 = __float2bfloat16(v.x - __bfloat162float(h0));
    __nv_bfloat16 l1 = __float2bfloat16(v.y - __bfloat162float(h1));
    __nv_bfloat16 l2 = __float2bfloat16(v.z - __bfloat162float(h2));
    __nv_bfloat16 l3 = __float2bfloat16(v.w - __bfloat162float(h3));
    reinterpret_cast<__nv_bfloat162*>(hi + i4)[0] = __nv_bfloat162(h0, h1);
    reinterpret_cast<__nv_bfloat162*>(hi + i4)[1] = __nv_bfloat162(h2, h3);
    reinterpret_cast<__nv_bfloat162*>(lo + i4)[0] = __nv_bfloat162(l0, l1);
    reinterpret_cast<__nv_bfloat162*>(lo + i4)[1] = __nv_bfloat162(l2, l3);
}

// ---------------------------------------------------------------------------
// mma.sync GEMM, bf16x3 split: C[8192,1024] = A @ B^T (fp32-accurate)
// Block 128x128, BK=32, 256 threads = 8 warps (2x4), warp tile 64x32.
// SMEM per stage: 4 arrays (Ahi,Alo,Bhi,Blo) of 128 rows x 40 bf16 (80B rows,
// conflict-free for both cp.async stores and ldmatrix). Double buffered.
// ---------------------------------------------------------------------------
#define GM_ROWB   80                     // bytes per smem row (40 bf16)
#define GM_ARR    (128 * GM_ROWB)        // 10240 B
#define GM_STAGE  (4 * GM_ARR)           // 40960 B
#define GM_SMEM   (2 * GM_STAGE)         // 81920 B
#define GM_CHUNKS 32                     // 1024 / 32

__device__ __forceinline__ void gm_load_stage(
    uint32_t sbase, const __nv_bfloat16* a_hi, const __nv_bfloat16* a_lo,
    const __nv_bfloat16* b_hi, const __nv_bfloat16* b_lo, int k0, int tid)
{
    const __nv_bfloat16* srcs[4] = {a_hi, a_lo, b_hi, b_lo};
    int seg = tid & 3;            // 16B segment within 64B of row data
    int r0  = tid >> 2;           // 0..63
#pragma unroll
    for (int arr = 0; arr < 4; arr++) {
        const __nv_bfloat16* s = srcs[arr] + k0 + seg * 8;
        uint32_t dst = sbase + arr * GM_ARR + seg * 16;
#pragma unroll
        for (int rr = 0; rr < 2; rr++) {
            int row = r0 + rr * 64;
            cp_async16(dst + row * GM_ROWB, s + (size_t)row * D_);
        }
    }
}

__global__ __launch_bounds__(256, 1) void gemm_mma_kernel(
    const __nv_bfloat16* __restrict__ Ahi, const __nv_bfloat16* __restrict__ Alo,
    const __nv_bfloat16* __restrict__ Bhi, const __nv_bfloat16* __restrict__ Blo,
    float* __restrict__ C)
{
    extern __shared__ __align__(128) char smem[];
    uint32_t sb = smem_to_u32(smem);

    const int tid  = threadIdx.x;
    const int wid  = tid >> 5;
    const int lane = tid & 31;
    const int wm = wid & 1;       // 2 warp rows (64 each)
    const int wn = wid >> 1;      // 4 warp cols (32 each)
    const int bm = blockIdx.y * 128;
    const int bn = blockIdx.x * 128;

    const __nv_bfloat16* a_hi = Ahi + (size_t)bm * D_;
    const __nv_bfloat16* a_lo = Alo + (size_t)bm * D_;
    const __nv_bfloat16* b_hi = Bhi + (size_t)bn * D_;
    const __nv_bfloat16* b_lo = Blo + (size_t)bn * D_;

    float c[4][4][4];
#pragma unroll
    for (int mt = 0; mt < 4; mt++)
#pragma unroll
        for (int nt = 0; nt < 4; nt++)
#pragma unroll
            for (int r = 0; r < 4; r++) c[mt][nt][r] = 0.0f;

    // ldmatrix lane addressing
    const int rowA = lane & 15;            // m row within 16
    const int kbA  = lane >> 4;            // 0/1 -> k halves (8 cols)
    const int rowB = (lane & 7) + ((lane >> 4) << 3);   // n row within 16
    const int kbB  = (lane >> 3) & 1;

    // base offsets (bytes) within a stage
    const uint32_t aoff = (uint32_t)(wm * 64 + rowA) * GM_ROWB + kbA * 16;
    const uint32_t boff = (uint32_t)(wn * 32 + rowB) * GM_ROWB + kbB * 16;

    // prologue
    gm_load_stage(sb, a_hi, a_lo, b_hi, b_lo, 0, tid);
    cp_commit();

    for (int i = 0; i < GM_CHUNKS; i++) {
        uint32_t st = sb + (i & 1) * GM_STAGE;
        if (i + 1 < GM_CHUNKS) {
            gm_load_stage(sb + ((i + 1) & 1) * GM_STAGE, a_hi, a_lo, b_hi, b_lo,
                          (i + 1) * 32, tid);
            cp_commit();
            cp_wait<1>();
        } else {
            cp_wait<0>();
        }
        __syncthreads();

#pragma unroll
        for (int ks = 0; ks < 2; ks++) {
            uint32_t koff = ks * 32;
            uint32_t ahi_a = st + 0 * GM_ARR + aoff + koff;
            uint32_t alo_a = st + 1 * GM_ARR + aoff + koff;
            uint32_t bhi_a = st + 2 * GM_ARR + boff + koff;
            uint32_t blo_a = st + 3 * GM_ARR + boff + koff;

            uint32_t fahi[4][4], falo[4][4], fbhi[2][4], fblo[2][4];
#pragma unroll
            for (int mt = 0; mt < 4; mt++) {
                ldsm_x4(fahi[mt], ahi_a + mt * 16 * GM_ROWB);
                ldsm_x4(falo[mt], alo_a + mt * 16 * GM_ROWB);
            }
#pragma unroll
            for (int np = 0; np < 2; np++) {
                ldsm_x4(fbhi[np], bhi_a + np * 16 * GM_ROWB);
                ldsm_x4(fblo[np], blo_a + np * 16 * GM_ROWB);
            }
#pragma unroll
            for (int mt = 0; mt < 4; mt++)
#pragma unroll
                for (int nt = 0; nt < 4; nt++) {
                    const uint32_t* bh = &fbhi[nt >> 1][(nt & 1) * 2];
                    const uint32_t* bl = &fblo[nt >> 1][(nt & 1) * 2];
                    mma_bf16(c[mt][nt], fahi[mt], bh);   // Ahi*Bhi
                    mma_bf16(c[mt][nt], falo[mt], bh);   // Alo*Bhi
                    mma_bf16(c[mt][nt], fahi[mt], bl);   // Ahi*Blo
                }
        }
        __syncthreads();
    }

    // epilogue: direct fp32 global stores
    const int erow = bm + wm * 64 + (lane >> 2);
    const int ecol = bn + wn * 32 + (lane & 3) * 2;
#pragma unroll
    for (int mt = 0; mt < 4; mt++)
#pragma unroll
        for (int nt = 0; nt < 4; nt++) {
            int r0 = erow + mt * 16;
            int cc = ecol + nt * 8;
            *(float2*)&C[(size_t)r0 * D_ + cc]       = make_float2(c[mt][nt][0], c[mt][nt][1]);
            *(float2*)&C[(size_t)(r0 + 8) * D_ + cc] = make_float2(c[mt][nt][2], c[mt][nt][3]);
        }
}

// ---------------------------------------------------------------------------
// RoPE tables, computed in fp64 (fast-math cosf is unsafe at theta ~ 2048 rad)
// ---------------------------------------------------------------------------
__global__ void rope_tables_kernel() {
    int i = blockIdx.x * blockDim.x + threadIdx.x;
    if (i >= T_ * 32) return;
    int t = i >> 5;
    int j = i & 31;
    float f32 = 0.0f;
    if (j < 16) f32 = (float)pow(1.0 / 1024.0, (double)j / 15.0);
    float theta = (float)t * f32;
    g_cos[i] = (float)cos((double)theta);
    g_sin[i] = (float)sin((double)theta);
}

// ---------------------------------------------------------------------------
// Fused per-head RMSNorm + RoPE for Q and K (in place)
// ---------------------------------------------------------------------------
__global__ __launch_bounds__(256) void norm_rope_kernel() {
    int gw   = (blockIdx.x * blockDim.x + threadIdx.x) >> 5;
    int lane = threadIdx.x & 31;
    if (gw >= NTOK * H_) return;

    int token = gw >> 4;
    int t = token & (T_ - 1);
    size_t base = (size_t)gw * 64;

    float c = g_cos[t * 32 + lane];
    float s = g_sin[t * 32 + lane];

    {   // Q
        float a  = g_q[base + lane];
        float b2 = g_q[base + lane + 32];
        float ss = a * a + b2 * b2;
#pragma unroll
        for (int m = 16; m > 0; m >>= 1) ss += __shfl_xor_sync(0xffffffffu, ss, m);
        float r = rsqrtf(ss * (1.0f / 64.0f) + 1e-6f);
        a *= r; b2 *= r;
        g_q[base + lane]      = a * c + b2 * s;
        g_q[base + lane + 32] = -a * s + b2 * c;
    }
    {   // K
        float a  = g_k[base + lane];
        float b2 = g_k[base + lane + 32];
        float ss = a * a + b2 * b2;
#pragma unroll
        for (int m = 16; m > 0; m >>= 1) ss += __shfl_xor_sync(0xffffffffu, ss, m);
        float r = rsqrtf(ss * (1.0f / 64.0f) + 1e-6f);
        a *= r; b2 *= r;
        g_k[base + lane]      = a * c + b2 * s;
        g_k[base + lane + 32] = -a * s + b2 * c;
    }
}

// ---------------------------------------------------------------------------
// Flash attention (causal), fp32 SIMT (tensor-core port is next round)
// ---------------------------------------------------------------------------
#define FPAD 68
#define FLASH_SMEM (4 * 64 * FPAD * 4)

__global__ __launch_bounds__(256) void flash_kernel(
    const float* __restrict__ Q, const float* __restrict__ K,
    const float* __restrict__ V, float* __restrict__ O)
{
    extern __shared__ float sm[];
    float* Qs  = sm;
    float* KsT = sm + 64 * FPAD;
    float* Vs  = KsT + 64 * FPAD;
    float* Ps  = Vs + 64 * FPAD;

    int qt = gridDim.x - 1 - blockIdx.x;
    int bh = blockIdx.y;
    int b = bh >> 4, h = bh & 15;

    int tid = threadIdx.x;
    int ty = tid >> 4, tx = tid & 15;
    int ri = ty << 2;

#pragma unroll
    for (int r = 0; r < 4; r++) {
        int row = (tid >> 4) + r * 16;
        int hd4 = (tid & 15) << 2;
        int t = qt * 64 + row;
        size_t gi = ((((size_t)b * T_ + t) * H_ + h) << 6) + hd4;
        float4 qv = *(const float4*)&Q[gi];
        *(float4*)&Qs[row * FPAD + hd4] =
            make_float4(qv.x * 0.125f, qv.y * 0.125f, qv.z * 0.125f, qv.w * 0.125f);
    }

    float m[4], l[4], acc[4][4];
#pragma unroll
    for (int i = 0; i < 4; i++) {
        m[i] = -1e30f; l[i] = 0.0f;
#pragma unroll
        for (int j = 0; j < 4; j++) acc[i][j] = 0.0f;
    }

    for (int jt = 0; jt <= qt; jt++) {
        __syncthreads();

#pragma unroll
        for (int r = 0; r < 4; r++) {
            int key = (tid >> 4) + r * 16;
            int hd4 = (tid & 15) << 2;
            int t = jt * 64 + key;
            size_t gi = ((((size_t)b * T_ + t) * H_ + h) << 6) + hd4;
            float4 kv = *(const float4*)&K[gi];
            KsT[(hd4 + 0) * FPAD + key] = kv.x;
            KsT[(hd4 + 1) * FPAD + key] = kv.y;
            KsT[(hd4 + 2) * FPAD + key] = kv.z;
            KsT[(hd4 + 3) * FPAD + key] = kv.w;
            float4 vv = *(const float4*)&V[gi];
            *(float4*)&Vs[key * FPAD + hd4] = vv;
        }
        __syncthreads();

        float s[4][4];
#pragma unroll
        for (int i = 0; i < 4; i++)
#pragma unroll
            for (int j = 0; j < 4; j++) s[i][j] = 0.0f;

#pragma unroll 8
        for (int kk = 0; kk < 64; kk++) {
            float q0 = Qs[(ri + 0) * FPAD + kk];
            float q1 = Qs[(ri + 1) * FPAD + kk];
            float q2 = Qs[(ri + 2) * FPAD + kk];
            float q3 = Qs[(ri + 3) * FPAD + kk];
            float4 k4 = *(const float4*)&KsT[kk * FPAD + (tx << 2)];
            s[0][0] = fmaf(q0, k4.x, s[0][0]); s[0][1] = fmaf(q0, k4.y, s[0][1]);
            s[0][2] = fmaf(q0, k4.z, s[0][2]); s[0][3] = fmaf(q0, k4.w, s[0][3]);
            s[1][0] = fmaf(q1, k4.x, s[1][0]); s[1][1] = fmaf(q1, k4.y, s[1][1]);
            s[1][2] = fmaf(q1, k4.z, s[1][2]); s[1][3] = fmaf(q1, k4.w, s[1][3]);
            s[2][0] = fmaf(q2, k4.x, s[2][0]); s[2][1] = fmaf(q2, k4.y, s[2][1]);
            s[2][2] = fmaf(q2, k4.z, s[2][2]); s[2][3] = fmaf(q2, k4.w, s[2][3]);
            s[3][0] = fmaf(q3, k4.x, s[3][0]); s[3][1] = fmaf(q3, k4.y, s[3][1]);
            s[3][2] = fmaf(q3, k4.z, s[3][2]); s[3][3] = fmaf(q3, k4.w, s[3][3]);
        }

        if (jt == qt) {
#pragma unroll
            for (int i = 0; i < 4; i++)
#pragma unroll
                for (int j = 0; j < 4; j++)
                    if ((tx << 2) + j > ri + i) s[i][j] = -1e30f;
        }

#pragma unroll
        for (int i = 0; i < 4; i++) {
            float mloc = fmaxf(fmaxf(s[i][0], s[i][1]), fmaxf(s[i][2], s[i][3]));
#pragma unroll
            for (int d = 8; d > 0; d >>= 1)
                mloc = fmaxf(mloc, __shfl_xor_sync(0xffffffffu, mloc, d));
            float mn = fmaxf(m[i], mloc);
            float alpha = __expf(m[i] - mn);
            float rs = 0.0f;
#pragma unroll
            for (int j = 0; j < 4; j++) {
                float p = __expf(s[i][j] - mn);
                s[i][j] = p;
                rs += p;
            }
#pragma unroll
            for (int d = 8; d > 0; d >>= 1)
                rs += __shfl_xor_sync(0xffffffffu, rs, d);
            l[i] = l[i] * alpha + rs;
            m[i] = mn;
#pragma unroll
            for (int j = 0; j < 4; j++) acc[i][j] *= alpha;
        }

#pragma unroll
        for (int i = 0; i < 4; i++)
            *(float4*)&Ps[(ri + i) * FPAD + (tx << 2)] =
                make_float4(s[i][0], s[i][1], s[i][2], s[i][3]);
        __syncthreads();

#pragma unroll 8
        for (int kk = 0; kk < 64; kk++) {
            float p0 = Ps[(ri + 0) * FPAD + kk];
            float p1 = Ps[(ri + 1) * FPAD + kk];
            float p2 = Ps[(ri + 2) * FPAD + kk];
            float p3 = Ps[(ri + 3) * FPAD + kk];
            float4 v4 = *(const float4*)&Vs[kk * FPAD + (tx << 2)];
            acc[0][0] = fmaf(p0, v4.x, acc[0][0]); acc[0][1] = fmaf(p0, v4.y, acc[0][1]);
            acc[0][2] = fmaf(p0, v4.z, acc[0][2]); acc[0][3] = fmaf(p0, v4.w, acc[0][3]);
            acc[1][0] = fmaf(p1, v4.x, acc[1][0]); acc[1][1] = fmaf(p1, v4.y, acc[1][1]);
            acc[1][2] = fmaf(p1, v4.z, acc[1][2]); acc[1][3] = fmaf(p1, v4.w, acc[1][3]);
            acc[2][0] = fmaf(p2, v4.x, acc[2][0]); acc[2][1] = fmaf(p2, v4.y, acc[2][1]);
            acc[2][2] = fmaf(p2, v4.z, acc[2][2]); acc[2][3] = fmaf(p2, v4.w, acc[2][3]);
            acc[3][0] = fmaf(p3, v4.x, acc[3][0]); acc[3][1] = fmaf(p3, v4.y, acc[3][1]);
            acc[3][2] = fmaf(p3, v4.z, acc[3][2]); acc[3][3] = fmaf(p3, v4.w, acc[3][3]);
        }
    }

#pragma unroll
    for (int i = 0; i < 4; i++) {
        float inv = 1.0f / l[i];
        int t = qt * 64 + ri + i;
        size_t gi = ((((size_t)b * T_ + t) * H_ + h) << 6) + (tx << 2);
        *(float4*)&O[gi] =
            make_float4(acc[i][0] * inv, acc[i][1] * inv, acc[i][2] * inv, acc[i][3] * inv);
    }
}

// ---------------------------------------------------------------------------
// Launch
// ---------------------------------------------------------------------------
extern "C" void kernel_launch(void* const* d_in, const int* in_sizes, int n_in,
                              void* d_out, int out_size)
{
    (void)in_sizes; (void)n_in; (void)out_size;
    const float* x  = (const float*)d_in[0];
    const float* w[4] = {(const float*)d_in[1], (const float*)d_in[2],
                         (const float*)d_in[3], (const float*)d_in[4]};
    float* out = (float*)d_out;

    float *qp, *kp, *vp, *op;
    __nv_bfloat16 *ahi, *alo, *whi, *wlo;
    cudaGetSymbolAddress((void**)&qp, g_q);
    cudaGetSymbolAddress((void**)&kp, g_k);
    cudaGetSymbolAddress((void**)&vp, g_v);
    cudaGetSymbolAddress((void**)&op, g_o);
    cudaGetSymbolAddress((void**)&ahi, g_ahi);
    cudaGetSymbolAddress((void**)&alo, g_alo);
    cudaGetSymbolAddress((void**)&whi, g_whi);
    cudaGetSymbolAddress((void**)&wlo, g_wlo);

    cudaFuncSetAttribute(gemm_mma_kernel,
                         cudaFuncAttributeMaxDynamicSharedMemorySize, GM_SMEM);
    cudaFuncSetAttribute(flash_kernel,
                         cudaFuncAttributeMaxDynamicSharedMemorySize, FLASH_SMEM);

    rope_tables_kernel<<<(T_ * 32 + 255) / 256, 256>>>();

    // splits: x and the 4 weights
    split_kernel<<<(NTOK * D_ / 4 + 255) / 256, 256>>>(x, ahi, alo, NTOK * D_);
    for (int i = 0; i < 4; i++)
        split_kernel<<<(D_ * D_ / 4 + 255) / 256, 256>>>(
            w[i], whi + (size_t)i * D_ * D_, wlo + (size_t)i * D_ * D_, D_ * D_);

    dim3 gg(D_ / 128, NTOK / 128);
    gemm_mma_kernel<<<gg, 256, GM_SMEM>>>(ahi, alo, whi + 0 * (size_t)D_ * D_,
                                          wlo + 0 * (size_t)D_ * D_, qp);
    gemm_mma_kernel<<<gg, 256, GM_SMEM>>>(ahi, alo, whi + 1 * (size_t)D_ * D_,
                                          wlo + 1 * (size_t)D_ * D_, kp);
    gemm_mma_kernel<<<gg, 256, GM_SMEM>>>(ahi, alo, whi + 2 * (size_t)D_ * D_,
                                          wlo + 2 * (size_t)D_ * D_, vp);

    norm_rope_kernel<<<(NTOK * H_) / 8, 256>>>();

    flash_kernel<<<dim3(T_ / 64, B_ * H_), 256, FLASH_SMEM>>>(qp, kp, vp, op);

    // split attention output (x buffers are dead now), final projection
    split_kernel<<<(NTOK * D_ / 4 + 255) / 256, 256>>>(op, ahi, alo, NTOK * D_);
    gemm_mma_kernel<<<gg, 256, GM_SMEM>>>(ahi, alo, whi + 3 * (size_t)D_ * D_,
                                          wlo + 3 * (size_t)D_ * D_, out);
}

// round 4
// speedup vs baseline: 2.4310x; 1.7469x over previous
#include <cuda_runtime.h>
#include <cuda_bf16.h>
#include <math.h>
#include <stdint.h>

// Problem constants
#define B_   4
#define T_   2048
#define D_   1024
#define H_   16
#define HD_  64
#define NTOK (B_ * T_)   // 8192
#define BH_  (B_ * H_)   // 64

// ---------------------------------------------------------------------------
// Scratch (device globals: allocation-free rule)
// ---------------------------------------------------------------------------
__device__ float g_q[NTOK * D_];
__device__ float g_k[NTOK * D_];
__device__ float g_v[NTOK * D_];
__device__ float g_o[NTOK * D_];
__device__ float g_cos[T_ * 32];
__device__ float g_sin[T_ * 32];

// bf16 hi/lo splits for projection GEMMs
__device__ __nv_bfloat16 g_ahi[NTOK * D_];
__device__ __nv_bfloat16 g_alo[NTOK * D_];
__device__ __nv_bfloat16 g_whi[4][D_ * D_];
__device__ __nv_bfloat16 g_wlo[4][D_ * D_];

// head-major bf16 hi/lo for flash attention: [bh][T][HD]
__device__ __nv_bfloat16 g_qhi[BH_ * T_ * HD_];
__device__ __nv_bfloat16 g_qlo[BH_ * T_ * HD_];
__device__ __nv_bfloat16 g_khi[BH_ * T_ * HD_];
__device__ __nv_bfloat16 g_klo[BH_ * T_ * HD_];
__device__ __nv_bfloat16 g_vhi[BH_ * T_ * HD_];
__device__ __nv_bfloat16 g_vlo[BH_ * T_ * HD_];

// ---------------------------------------------------------------------------
// PTX helpers (base compute_103 target: mma.sync / ldmatrix / cp.async only)
// ---------------------------------------------------------------------------
__device__ __forceinline__ uint32_t smem_to_u32(const void* p) {
    uint32_t a;
    asm("{ .reg .u64 t; cvta.to.shared.u64 t, %1; cvt.u32.u64 %0, t; }"
        : "=r"(a) : "l"(p));
    return a;
}

__device__ __forceinline__ void ldsm_x4(uint32_t* r, uint32_t addr) {
    asm volatile("ldmatrix.sync.aligned.m8n8.x4.shared.b16 {%0,%1,%2,%3}, [%4];"
                 : "=r"(r[0]), "=r"(r[1]), "=r"(r[2]), "=r"(r[3]) : "r"(addr));
}

__device__ __forceinline__ void ldsm_x4_t(uint32_t* r, uint32_t addr) {
    asm volatile("ldmatrix.sync.aligned.m8n8.x4.trans.shared.b16 {%0,%1,%2,%3}, [%4];"
                 : "=r"(r[0]), "=r"(r[1]), "=r"(r[2]), "=r"(r[3]) : "r"(addr));
}

__device__ __forceinline__ void mma_bf16(float* c, const uint32_t* a, const uint32_t* b) {
    asm volatile(
        "mma.sync.aligned.m16n8k16.row.col.f32.bf16.bf16.f32 "
        "{%0,%1,%2,%3}, {%4,%5,%6,%7}, {%8,%9}, {%0,%1,%2,%3};"
        : "+f"(c[0]), "+f"(c[1]), "+f"(c[2]), "+f"(c[3])
        : "r"(a[0]), "r"(a[1]), "r"(a[2]), "r"(a[3]), "r"(b[0]), "r"(b[1]));
}

__device__ __forceinline__ void cp_async16(uint32_t dst, const void* src) {
    asm volatile("cp.async.cg.shared.global [%0], [%1], 16;"
                 :: "r"(dst), "l"(src));
}
__device__ __forceinline__ void cp_commit() {
    asm volatile("cp.async.commit_group;" ::: "memory");
}
template <int N>
__device__ __forceinline__ void cp_wait() {
    asm volatile("cp.async.wait_group %0;" :: "n"(N) : "memory");
}

// pack two fp32 into bf16x2 register: lo half = first mma element (even k)
__device__ __forceinline__ uint32_t pack_bf16x2(float lo, float hi) {
    uint32_t r;
    asm("cvt.rn.bf16x2.f32 %0, %1, %2;" : "=r"(r) : "f"(hi), "f"(lo));
    return r;
}

// ---------------------------------------------------------------------------
// fp32 -> (bf16 hi, bf16 lo) split (flat layout)
// ---------------------------------------------------------------------------
__global__ __launch_bounds__(256) void split_kernel(
    const float* __restrict__ src, __nv_bfloat16* __restrict__ hi,
    __nv_bfloat16* __restrict__ lo, int n)
{
    int i4 = (blockIdx.x * blockDim.x + threadIdx.x) * 4;
    if (i4 >= n) return;
    float4 v = *(const float4*)(src + i4);
    __nv_bfloat16 h0 = __float2bfloat16(v.x);
    __nv_bfloat16 h1 = __float2bfloat16(v.y);
    __nv_bfloat16 h2 = __float2bfloat16(v.z);
    __nv_bfloat16 h3 = __float2bfloat16(v.w);
    __nv_bfloat16 l0 = __float2bfloat16(v.x - __bfloat162float(h0));
    __nv_bfloat16 l1 = __float2bfloat16(v.y - __bfloat162float(h1));
    __nv_bfloat16 l2 = __float2bfloat16(v.z - __bfloat162float(h2));
    __nv_bfloat16 l3 = __float2bfloat16(v.w - __bfloat162float(h3));
    reinterpret_cast<__nv_bfloat162*>(hi + i4)[0] = __nv_bfloat162(h0, h1);
    reinterpret_cast<__nv_bfloat162*>(hi + i4)[1] = __nv_bfloat162(h2, h3);
    reinterpret_cast<__nv_bfloat162*>(lo + i4)[0] = __nv_bfloat162(l0, l1);
    reinterpret_cast<__nv_bfloat162*>(lo + i4)[1] = __nv_bfloat162(l2, l3);
}

// V: token-major fp32 -> head-major bf16 hi/lo
__global__ __launch_bounds__(256) void split_v_kernel() {
    int i4 = (blockIdx.x * blockDim.x + threadIdx.x) * 4;
    if (i4 >= NTOK * D_) return;
    int token = i4 >> 10;
    int rem = i4 & 1023;
    int h = rem >> 6, c = rem & 63;
    int b = token >> 11, t = token & (T_ - 1);
    size_t oi = (((size_t)(b * H_ + h)) * T_ + t) * HD_ + c;
    float4 v = *(const float4*)(g_v + i4);
    __nv_bfloat16 h0 = __float2bfloat16(v.x);
    __nv_bfloat16 h1 = __float2bfloat16(v.y);
    __nv_bfloat16 h2 = __float2bfloat16(v.z);
    __nv_bfloat16 h3 = __float2bfloat16(v.w);
    reinterpret_cast<__nv_bfloat162*>(g_vhi + oi)[0] = __nv_bfloat162(h0, h1);
    reinterpret_cast<__nv_bfloat162*>(g_vhi + oi)[1] = __nv_bfloat162(h2, h3);
    reinterpret_cast<__nv_bfloat162*>(g_vlo + oi)[0] = __nv_bfloat162(
        __float2bfloat16(v.x - __bfloat162float(h0)),
        __float2bfloat16(v.y - __bfloat162float(h1)));
    reinterpret_cast<__nv_bfloat162*>(g_vlo + oi)[1] = __nv_bfloat162(
        __float2bfloat16(v.z - __bfloat162float(h2)),
        __float2bfloat16(v.w - __bfloat162float(h3)));
}

// ---------------------------------------------------------------------------
// mma.sync GEMM, bf16x3 split: C[8192,1024] = A @ B^T (unchanged from R3)
// ---------------------------------------------------------------------------
#define GM_ROWB   80
#define GM_ARR    (128 * GM_ROWB)
#define GM_STAGE  (4 * GM_ARR)
#define GM_SMEM   (2 * GM_STAGE)
#define GM_CHUNKS 32

__device__ __forceinline__ void gm_load_stage(
    uint32_t sbase, const __nv_bfloat16* a_hi, const __nv_bfloat16* a_lo,
    const __nv_bfloat16* b_hi, const __nv_bfloat16* b_lo, int k0, int tid)
{
    const __nv_bfloat16* srcs[4] = {a_hi, a_lo, b_hi, b_lo};
    int seg = tid & 3;
    int r0  = tid >> 2;
#pragma unroll
    for (int arr = 0; arr < 4; arr++) {
        const __nv_bfloat16* s = srcs[arr] + k0 + seg * 8;
        uint32_t dst = sbase + arr * GM_ARR + seg * 16;
#pragma unroll
        for (int rr = 0; rr < 2; rr++) {
            int row = r0 + rr * 64;
            cp_async16(dst + row * GM_ROWB, s + (size_t)row * D_);
        }
    }
}

__global__ __launch_bounds__(256, 1) void gemm_mma_kernel(
    const __nv_bfloat16* __restrict__ Ahi, const __nv_bfloat16* __restrict__ Alo,
    const __nv_bfloat16* __restrict__ Bhi, const __nv_bfloat16* __restrict__ Blo,
    float* __restrict__ C)
{
    extern __shared__ __align__(128) char smem[];
    uint32_t sb = smem_to_u32(smem);

    const int tid  = threadIdx.x;
    const int wid  = tid >> 5;
    const int lane = tid & 31;
    const int wm = wid & 1;
    const int wn = wid >> 1;
    const int bm = blockIdx.y * 128;
    const int bn = blockIdx.x * 128;

    const __nv_bfloat16* a_hi = Ahi + (size_t)bm * D_;
    const __nv_bfloat16* a_lo = Alo + (size_t)bm * D_;
    const __nv_bfloat16* b_hi = Bhi + (size_t)bn * D_;
    const __nv_bfloat16* b_lo = Blo + (size_t)bn * D_;

    float c[4][4][4];
#pragma unroll
    for (int mt = 0; mt < 4; mt++)
#pragma unroll
        for (int nt = 0; nt < 4; nt++)
#pragma unroll
            for (int r = 0; r < 4; r++) c[mt][nt][r] = 0.0f;

    const int rowA = lane & 15;
    const int kbA  = lane >> 4;
    const int rowB = (lane & 7) + ((lane >> 4) << 3);
    const int kbB  = (lane >> 3) & 1;

    const uint32_t aoff = (uint32_t)(wm * 64 + rowA) * GM_ROWB + kbA * 16;
    const uint32_t boff = (uint32_t)(wn * 32 + rowB) * GM_ROWB + kbB * 16;

    gm_load_stage(sb, a_hi, a_lo, b_hi, b_lo, 0, tid);
    cp_commit();

    for (int i = 0; i < GM_CHUNKS; i++) {
        uint32_t st = sb + (i & 1) * GM_STAGE;
        if (i + 1 < GM_CHUNKS) {
            gm_load_stage(sb + ((i + 1) & 1) * GM_STAGE, a_hi, a_lo, b_hi, b_lo,
                          (i + 1) * 32, tid);
            cp_commit();
            cp_wait<1>();
        } else {
            cp_wait<0>();
        }
        __syncthreads();

#pragma unroll
        for (int ks = 0; ks < 2; ks++) {
            uint32_t koff = ks * 32;
            uint32_t ahi_a = st + 0 * GM_ARR + aoff + koff;
            uint32_t alo_a = st + 1 * GM_ARR + aoff + koff;
            uint32_t bhi_a = st + 2 * GM_ARR + boff + koff;
            uint32_t blo_a = st + 3 * GM_ARR + boff + koff;

            uint32_t fahi[4][4], falo[4][4], fbhi[2][4], fblo[2][4];
#pragma unroll
            for (int mt = 0; mt < 4; mt++) {
                ldsm_x4(fahi[mt], ahi_a + mt * 16 * GM_ROWB);
                ldsm_x4(falo[mt], alo_a + mt * 16 * GM_ROWB);
            }
#pragma unroll
            for (int np = 0; np < 2; np++) {
                ldsm_x4(fbhi[np], bhi_a + np * 16 * GM_ROWB);
                ldsm_x4(fblo[np], blo_a + np * 16 * GM_ROWB);
            }
#pragma unroll
            for (int mt = 0; mt < 4; mt++)
#pragma unroll
                for (int nt = 0; nt < 4; nt++) {
                    const uint32_t* bh = &fbhi[nt >> 1][(nt & 1) * 2];
                    const uint32_t* bl = &fblo[nt >> 1][(nt & 1) * 2];
                    mma_bf16(c[mt][nt], fahi[mt], bh);
                    mma_bf16(c[mt][nt], falo[mt], bh);
                    mma_bf16(c[mt][nt], fahi[mt], bl);
                }
        }
        __syncthreads();
    }

    const int erow = bm + wm * 64 + (lane >> 2);
    const int ecol = bn + wn * 32 + (lane & 3) * 2;
#pragma unroll
    for (int mt = 0; mt < 4; mt++)
#pragma unroll
        for (int nt = 0; nt < 4; nt++) {
            int r0 = erow + mt * 16;
            int cc = ecol + nt * 8;
            *(float2*)&C[(size_t)r0 * D_ + cc]       = make_float2(c[mt][nt][0], c[mt][nt][1]);
            *(float2*)&C[(size_t)(r0 + 8) * D_ + cc] = make_float2(c[mt][nt][2], c[mt][nt][3]);
        }
}

// ---------------------------------------------------------------------------
// RoPE tables in fp64 (fast-math cosf unsafe at theta ~ 2048 rad)
// ---------------------------------------------------------------------------
__global__ void rope_tables_kernel() {
    int i = blockIdx.x * blockDim.x + threadIdx.x;
    if (i >= T_ * 32) return;
    int t = i >> 5;
    int j = i & 31;
    float f32 = 0.0f;
    if (j < 16) f32 = (float)pow(1.0 / 1024.0, (double)j / 15.0);
    float theta = (float)t * f32;
    g_cos[i] = (float)cos((double)theta);
    g_sin[i] = (float)sin((double)theta);
}

// ---------------------------------------------------------------------------
// Fused per-head RMSNorm + RoPE; writes head-major bf16 hi/lo.
// Q additionally scaled by 1/sqrt(HD) = 0.125 (exact power of two).
// ---------------------------------------------------------------------------
__global__ __launch_bounds__(256) void norm_rope_kernel() {
    int gw   = (blockIdx.x * blockDim.x + threadIdx.x) >> 5;
    int lane = threadIdx.x & 31;
    if (gw >= NTOK * H_) return;

    int token = gw >> 4;
    int h = gw & 15;
    int b = token >> 11;
    int t = token & (T_ - 1);
    size_t base = (size_t)gw * 64;                              // token-major fp32
    size_t hb = (((size_t)(b * H_ + h)) * T_ + t) * HD_;        // head-major bf16

    float c = g_cos[t * 32 + lane];
    float s = g_sin[t * 32 + lane];

    {   // Q (scaled by 0.125)
        float a  = g_q[base + lane];
        float b2 = g_q[base + lane + 32];
        float ss = a * a + b2 * b2;
#pragma unroll
        for (int m = 16; m > 0; m >>= 1) ss += __shfl_xor_sync(0xffffffffu, ss, m);
        float r = rsqrtf(ss * (1.0f / 64.0f) + 1e-6f);
        a *= r; b2 *= r;
        float y1 = (a * c + b2 * s) * 0.125f;
        float y2 = (-a * s + b2 * c) * 0.125f;
        __nv_bfloat16 h1 = __float2bfloat16(y1);
        __nv_bfloat16 h2 = __float2bfloat16(y2);
        g_qhi[hb + lane]      = h1;
        g_qhi[hb + lane + 32] = h2;
        g_qlo[hb + lane]      = __float2bfloat16(y1 - __bfloat162float(h1));
        g_qlo[hb + lane + 32] = __float2bfloat16(y2 - __bfloat162float(h2));
    }
    {   // K
        float a  = g_k[base + lane];
        float b2 = g_k[base + lane + 32];
        float ss = a * a + b2 * b2;
#pragma unroll
        for (int m = 16; m > 0; m >>= 1) ss += __shfl_xor_sync(0xffffffffu, ss, m);
        float r = rsqrtf(ss * (1.0f / 64.0f) + 1e-6f);
        a *= r; b2 *= r;
        float y1 = a * c + b2 * s;
        float y2 = -a * s + b2 * c;
        __nv_bfloat16 h1 = __float2bfloat16(y1);
        __nv_bfloat16 h2 = __float2bfloat16(y2);
        g_khi[hb + lane]      = h1;
        g_khi[hb + lane + 32] = h2;
        g_klo[hb + lane]      = __float2bfloat16(y1 - __bfloat162float(h1));
        g_klo[hb + lane + 32] = __float2bfloat16(y2 - __bfloat162float(h2));
    }
}

// ---------------------------------------------------------------------------
// Flash attention via mma.sync, bf16x3 (causal).
// CTA: 128 queries x full key loop (64-key tiles), 8 warps = 16 rows each.
// SMEM rows padded to 144B (conflict-free cp.async stores + ldmatrix).
// ---------------------------------------------------------------------------
#define FROWB   144u
#define FQ_SIZE (128 * 144)         // one Q array (hi or lo)
#define FKV_OFF (2 * FQ_SIZE)       // 36864
#define FKV_ARR (64 * 144)          // 9216
#define FSTAGE  (4 * FKV_ARR)       // 36864: khi, klo, vhi, vlo
#define FMMA_SMEM (FKV_OFF + 2 * FSTAGE)   // 110592

__device__ __forceinline__ void f_load_kv(
    uint32_t dst, const __nv_bfloat16* kh, const __nv_bfloat16* kl,
    const __nv_bfloat16* vh, const __nv_bfloat16* vl, size_t goff, int tid)
{
    const __nv_bfloat16* srcs[4] = {kh, kl, vh, vl};
    int seg = tid & 7, r0 = tid >> 3;
#pragma unroll
    for (int arr = 0; arr < 4; arr++) {
        const __nv_bfloat16* s = srcs[arr] + goff + seg * 8;
        uint32_t d = dst + arr * FKV_ARR + seg * 16;
#pragma unroll
        for (int rr = 0; rr < 2; rr++) {
            int row = r0 + rr * 32;
            cp_async16(d + row * FROWB, s + row * HD_);
        }
    }
}

__global__ __launch_bounds__(256, 1) void flash_mma_kernel(
    const __nv_bfloat16* __restrict__ Qhi, const __nv_bfloat16* __restrict__ Qlo,
    const __nv_bfloat16* __restrict__ Khi, const __nv_bfloat16* __restrict__ Klo,
    const __nv_bfloat16* __restrict__ Vhi, const __nv_bfloat16* __restrict__ Vlo,
    float* __restrict__ O)
{
    extern __shared__ __align__(128) char fsm[];
    uint32_t sb = smem_to_u32(fsm);
    const int tid = threadIdx.x, wid = tid >> 5, lane = tid & 31;
    const int bh = blockIdx.x;
    const int qt = 15 - blockIdx.y;          // big tiles scheduled first
    const int b = bh >> 4, h = bh & 15;
    const size_t headoff = (size_t)bh * T_ * HD_;
    const int nkt = 2 * qt + 2;              // 64-key tiles

    // prologue: Q (hi+lo) and KV stage 0 in one cp.async group
    {
        int seg = tid & 7, r0 = tid >> 3;
        const __nv_bfloat16* q0 = Qhi + headoff + (size_t)qt * 128 * HD_ + seg * 8;
        const __nv_bfloat16* q1 = Qlo + headoff + (size_t)qt * 128 * HD_ + seg * 8;
#pragma unroll
        for (int rr = 0; rr < 4; rr++) {
            int row = r0 + rr * 32;
            cp_async16(sb + row * FROWB + seg * 16, q0 + row * HD_);
            cp_async16(sb + FQ_SIZE + row * FROWB + seg * 16, q1 + row * HD_);
        }
    }
    f_load_kv(sb + FKV_OFF, Khi, Klo, Vhi, Vlo, headoff, tid);
    cp_commit();

    // persistent state
    uint32_t fqh[4][4], fql[4][4];
    float o[8][4];
#pragma unroll
    for (int nt = 0; nt < 8; nt++)
#pragma unroll
        for (int r = 0; r < 4; r++) o[nt][r] = 0.0f;
    float m0 = -1e30f, m1 = -1e30f, l0 = 0.0f, l1 = 0.0f;

    // fragment addressing
    const uint32_t qrow_off = (uint32_t)(wid * 16 + (lane & 15)) * FROWB + (lane >> 4) * 16;
    const uint32_t krow_off = (uint32_t)((lane & 7) + ((lane >> 4) << 3)) * FROWB
                              + ((lane >> 3) & 1) * 16;
    const uint32_t vrow_off = (uint32_t)(lane & 15) * FROWB + (lane >> 4) * 16;

    for (int jt = 0; jt < nkt; jt++) {
        if (jt + 1 < nkt) {
            f_load_kv(sb + FKV_OFF + ((jt + 1) & 1) * FSTAGE, Khi, Klo, Vhi, Vlo,
                      headoff + (size_t)(jt + 1) * 64 * HD_, tid);
            cp_commit();
            cp_wait<1>();
        } else {
            cp_wait<0>();
        }
        __syncthreads();

        if (jt == 0) {   // Q fragments, loaded once
#pragma unroll
            for (int ks = 0; ks < 4; ks++) {
                ldsm_x4(fqh[ks], sb + qrow_off + ks * 32);
                ldsm_x4(fql[ks], sb + FQ_SIZE + qrow_off + ks * 32);
            }
        }

        uint32_t st = sb + FKV_OFF + (jt & 1) * FSTAGE;

        // S = Q K^T (3 passes)
        float s[8][4];
#pragma unroll
        for (int nt = 0; nt < 8; nt++)
#pragma unroll
            for (int r = 0; r < 4; r++) s[nt][r] = 0.0f;

#pragma unroll
        for (int np = 0; np < 4; np++) {
#pragma unroll
            for (int ks = 0; ks < 4; ks++) {
                uint32_t addr = st + krow_off + np * 16 * FROWB + ks * 32;
                uint32_t fk[4];
                ldsm_x4(fk, addr);                 // Khi
                mma_bf16(s[2 * np],     fqh[ks], fk + 0);
                mma_bf16(s[2 * np + 1], fqh[ks], fk + 2);
                mma_bf16(s[2 * np],     fql[ks], fk + 0);
                mma_bf16(s[2 * np + 1], fql[ks], fk + 2);
                ldsm_x4(fk, addr + FKV_ARR);       // Klo
                mma_bf16(s[2 * np],     fqh[ks], fk + 0);
                mma_bf16(s[2 * np + 1], fqh[ks], fk + 2);
            }
        }

        // causal mask on the diagonal 128-block
        if (jt >= 2 * qt) {
            int grow = qt * 128 + wid * 16 + (lane >> 2);
            int gc0 = jt * 64 + (lane & 3) * 2;
#pragma unroll
            for (int nt = 0; nt < 8; nt++) {
                int cc = gc0 + nt * 8;
                if (cc > grow)          s[nt][0] = -1e30f;
                if (cc + 1 > grow)      s[nt][1] = -1e30f;
                if (cc > grow + 8)      s[nt][2] = -1e30f;
                if (cc + 1 > grow + 8)  s[nt][3] = -1e30f;
            }
        }

        // online softmax (rows r = lane>>2 and r+8; quad lanes share rows)
        float mx0 = -1e30f, mx1 = -1e30f;
#pragma unroll
        for (int nt = 0; nt < 8; nt++) {
            mx0 = fmaxf(mx0, fmaxf(s[nt][0], s[nt][1]));
            mx1 = fmaxf(mx1, fmaxf(s[nt][2], s[nt][3]));
        }
        mx0 = fmaxf(mx0, __shfl_xor_sync(0xffffffffu, mx0, 1));
        mx0 = fmaxf(mx0, __shfl_xor_sync(0xffffffffu, mx0, 2));
        mx1 = fmaxf(mx1, __shfl_xor_sync(0xffffffffu, mx1, 1));
        mx1 = fmaxf(mx1, __shfl_xor_sync(0xffffffffu, mx1, 2));
        float mn0 = fmaxf(m0, mx0), mn1 = fmaxf(m1, mx1);
        float al0 = __expf(m0 - mn0), al1 = __expf(m1 - mn1);
        float rs0 = 0.0f, rs1 = 0.0f;
#pragma unroll
        for (int nt = 0; nt < 8; nt++) {
            s[nt][0] = __expf(s[nt][0] - mn0);
            s[nt][1] = __expf(s[nt][1] - mn0);
            s[nt][2] = __expf(s[nt][2] - mn1);
            s[nt][3] = __expf(s[nt][3] - mn1);
            rs0 += s[nt][0] + s[nt][1];
            rs1 += s[nt][2] + s[nt][3];
        }
        rs0 += __shfl_xor_sync(0xffffffffu, rs0, 1);
        rs0 += __shfl_xor_sync(0xffffffffu, rs0, 2);
        rs1 += __shfl_xor_sync(0xffffffffu, rs1, 1);
        rs1 += __shfl_xor_sync(0xffffffffu, rs1, 2);
        l0 = l0 * al0 + rs0; m0 = mn0;
        l1 = l1 * al1 + rs1; m1 = mn1;
#pragma unroll
        for (int nt = 0; nt < 8; nt++) {
            o[nt][0] *= al0; o[nt][1] *= al0;
            o[nt][2] *= al1; o[nt][3] *= al1;
        }

        // P -> bf16 hi/lo A-fragments (in registers)
        uint32_t fph[4][4], fpl[4][4];
#pragma unroll
        for (int f = 0; f < 4; f++) {
#pragma unroll
            for (int half = 0; half < 2; half++) {     // half 0: k low 8 (nt=2f), 1: k high (2f+1)
                int nt = 2 * f + half;
#pragma unroll
                for (int rh = 0; rh < 2; rh++) {       // rh 0: row r, 1: row r+8
                    float p0 = s[nt][rh * 2], p1 = s[nt][rh * 2 + 1];
                    uint32_t hi = pack_bf16x2(p0, p1);
                    float h0 = __uint_as_float(hi << 16);
                    float h1 = __uint_as_float(hi & 0xFFFF0000u);
                    uint32_t lo = pack_bf16x2(p0 - h0, p1 - h1);
                    fph[f][half * 2 + rh] = hi;
                    fpl[f][half * 2 + rh] = lo;
                }
            }
        }

        // O += P V (3 passes), V^T fragments via ldmatrix.trans
#pragma unroll
        for (int nh = 0; nh < 4; nh++) {
#pragma unroll
            for (int ks = 0; ks < 4; ks++) {
                uint32_t addr = st + 2 * FKV_ARR + vrow_off + ks * 16 * FROWB + nh * 32;
                uint32_t fv[4];
                ldsm_x4_t(fv, addr);               // Vhi
                mma_bf16(o[2 * nh],     fph[ks], fv + 0);
                mma_bf16(o[2 * nh + 1], fph[ks], fv + 2);
                mma_bf16(o[2 * nh],     fpl[ks], fv + 0);
                mma_bf16(o[2 * nh + 1], fpl[ks], fv + 2);
                ldsm_x4_t(fv, addr + FKV_ARR);     // Vlo
                mma_bf16(o[2 * nh],     fph[ks], fv + 0);
                mma_bf16(o[2 * nh + 1], fph[ks], fv + 2);
            }
        }
        __syncthreads();
    }

    // epilogue: normalize, write token-major fp32 [b][t][h*64+hd]
    float inv0 = 1.0f / l0, inv1 = 1.0f / l1;
    int row = qt * 128 + wid * 16 + (lane >> 2);
    float* op0 = O + ((size_t)b * T_ + row) * D_ + h * 64 + (lane & 3) * 2;
    float* op1 = op0 + 8 * D_;
#pragma unroll
    for (int nt = 0; nt < 8; nt++) {
        *(float2*)(op0 + nt * 8) = make_float2(o[nt][0] * inv0, o[nt][1] * inv0);
        *(float2*)(op1 + nt * 8) = make_float2(o[nt][2] * inv1, o[nt][3] * inv1);
    }
}

// ---------------------------------------------------------------------------
// Launch
// ---------------------------------------------------------------------------
extern "C" void kernel_launch(void* const* d_in, const int* in_sizes, int n_in,
                              void* d_out, int out_size)
{
    (void)in_sizes; (void)n_in; (void)out_size;
    const float* x  = (const float*)d_in[0];
    const float* w[4] = {(const float*)d_in[1], (const float*)d_in[2],
                         (const float*)d_in[3], (const float*)d_in[4]};
    float* out = (float*)d_out;

    float *qp, *kp, *vp, *op;
    __nv_bfloat16 *ahi, *alo, *whi, *wlo;
    __nv_bfloat16 *qhi, *qlo, *khi, *klo, *vhi, *vlo;
    cudaGetSymbolAddress((void**)&qp, g_q);
    cudaGetSymbolAddress((void**)&kp, g_k);
    cudaGetSymbolAddress((void**)&vp, g_v);
    cudaGetSymbolAddress((void**)&op, g_o);
    cudaGetSymbolAddress((void**)&ahi, g_ahi);
    cudaGetSymbolAddress((void**)&alo, g_alo);
    cudaGetSymbolAddress((void**)&whi, g_whi);
    cudaGetSymbolAddress((void**)&wlo, g_wlo);
    cudaGetSymbolAddress((void**)&qhi, g_qhi);
    cudaGetSymbolAddress((void**)&qlo, g_qlo);
    cudaGetSymbolAddress((void**)&khi, g_khi);
    cudaGetSymbolAddress((void**)&klo, g_klo);
    cudaGetSymbolAddress((void**)&vhi, g_vhi);
    cudaGetSymbolAddress((void**)&vlo, g_vlo);

    cudaFuncSetAttribute(gemm_mma_kernel,
                         cudaFuncAttributeMaxDynamicSharedMemorySize, GM_SMEM);
    cudaFuncSetAttribute(flash_mma_kernel,
                         cudaFuncAttributeMaxDynamicSharedMemorySize, FMMA_SMEM);

    rope_tables_kernel<<<(T_ * 32 + 255) / 256, 256>>>();

    split_kernel<<<(NTOK * D_ / 4 + 255) / 256, 256>>>(x, ahi, alo, NTOK * D_);
    for (int i = 0; i < 4; i++)
        split_kernel<<<(D_ * D_ / 4 + 255) / 256, 256>>>(
            w[i], whi + (size_t)i * D_ * D_, wlo + (size_t)i * D_ * D_, D_ * D_);

    dim3 gg(D_ / 128, NTOK / 128);
    gemm_mma_kernel<<<gg, 256, GM_SMEM>>>(ahi, alo, whi + 0 * (size_t)D_ * D_,
                                          wlo + 0 * (size_t)D_ * D_, qp);
    gemm_mma_kernel<<<gg, 256, GM_SMEM>>>(ahi, alo, whi + 1 * (size_t)D_ * D_,
                                          wlo + 1 * (size_t)D_ * D_, kp);
    gemm_mma_kernel<<<gg, 256, GM_SMEM>>>(ahi, alo, whi + 2 * (size_t)D_ * D_,
                                          wlo + 2 * (size_t)D_ * D_, vp);

    norm_rope_kernel<<<(NTOK * H_) / 8, 256>>>();
    split_v_kernel<<<(NTOK * D_ / 4 + 255) / 256, 256>>>();

    flash_mma_kernel<<<dim3(BH_, T_ / 128), 256, FMMA_SMEM>>>(
        qhi, qlo, khi, klo, vhi, vlo, op);

    split_kernel<<<(NTOK * D_ / 4 + 255) / 256, 256>>>(op, ahi, alo, NTOK * D_);
    gemm_mma_kernel<<<gg, 256, GM_SMEM>>>(ahi, alo, whi + 3 * (size_t)D_ * D_,
                                          wlo + 3 * (size_t)D_ * D_, out);
}

// round 5
// speedup vs baseline: 2.7394x; 1.1269x over previous
#include <cuda_runtime.h>
#include <cuda_bf16.h>
#include <math.h>
#include <stdint.h>

// Problem constants
#define B_   4
#define T_   2048
#define D_   1024
#define H_   16
#define HD_  64
#define NTOK (B_ * T_)   // 8192
#define BH_  (B_ * H_)   // 64

// ---------------------------------------------------------------------------
// Scratch (device globals: allocation-free rule)
// ---------------------------------------------------------------------------
__device__ float g_q[NTOK * D_];
__device__ float g_k[NTOK * D_];
__device__ float g_v[NTOK * D_];
__device__ float g_o[NTOK * D_];
__device__ float g_cos[T_ * 32];
__device__ float g_sin[T_ * 32];

// bf16 hi/lo splits for projection GEMMs
__device__ __nv_bfloat16 g_ahi[NTOK * D_];
__device__ __nv_bfloat16 g_alo[NTOK * D_];
__device__ __nv_bfloat16 g_whi[4][D_ * D_];
__device__ __nv_bfloat16 g_wlo[4][D_ * D_];

// head-major bf16 hi/lo for flash attention: [bh][T][HD]
__device__ __nv_bfloat16 g_qhi[BH_ * T_ * HD_];
__device__ __nv_bfloat16 g_qlo[BH_ * T_ * HD_];
__device__ __nv_bfloat16 g_khi[BH_ * T_ * HD_];
__device__ __nv_bfloat16 g_klo[BH_ * T_ * HD_];
__device__ __nv_bfloat16 g_vhi[BH_ * T_ * HD_];
__device__ __nv_bfloat16 g_vlo[BH_ * T_ * HD_];

// ---------------------------------------------------------------------------
// PTX helpers (base compute_103 target: mma.sync / ldmatrix / cp.async only)
// ---------------------------------------------------------------------------
__device__ __forceinline__ uint32_t smem_to_u32(const void* p) {
    uint32_t a;
    asm("{ .reg .u64 t; cvta.to.shared.u64 t, %1; cvt.u32.u64 %0, t; }"
        : "=r"(a) : "l"(p));
    return a;
}

__device__ __forceinline__ void ldsm_x4(uint32_t* r, uint32_t addr) {
    asm volatile("ldmatrix.sync.aligned.m8n8.x4.shared.b16 {%0,%1,%2,%3}, [%4];"
                 : "=r"(r[0]), "=r"(r[1]), "=r"(r[2]), "=r"(r[3]) : "r"(addr));
}

__device__ __forceinline__ void ldsm_x4_t(uint32_t* r, uint32_t addr) {
    asm volatile("ldmatrix.sync.aligned.m8n8.x4.trans.shared.b16 {%0,%1,%2,%3}, [%4];"
                 : "=r"(r[0]), "=r"(r[1]), "=r"(r[2]), "=r"(r[3]) : "r"(addr));
}

__device__ __forceinline__ void mma_bf16(float* c, const uint32_t* a, const uint32_t* b) {
    asm volatile(
        "mma.sync.aligned.m16n8k16.row.col.f32.bf16.bf16.f32 "
        "{%0,%1,%2,%3}, {%4,%5,%6,%7}, {%8,%9}, {%0,%1,%2,%3};"
        : "+f"(c[0]), "+f"(c[1]), "+f"(c[2]), "+f"(c[3])
        : "r"(a[0]), "r"(a[1]), "r"(a[2]), "r"(a[3]), "r"(b[0]), "r"(b[1]));
}

__device__ __forceinline__ void cp_async16(uint32_t dst, const void* src) {
    asm volatile("cp.async.cg.shared.global [%0], [%1], 16;"
                 :: "r"(dst), "l"(src));
}
__device__ __forceinline__ void cp_commit() {
    asm volatile("cp.async.commit_group;" ::: "memory");
}
template <int N>
__device__ __forceinline__ void cp_wait() {
    asm volatile("cp.async.wait_group %0;" :: "n"(N) : "memory");
}

__device__ __forceinline__ uint32_t pack_bf16x2(float lo, float hi) {
    uint32_t r;
    asm("cvt.rn.bf16x2.f32 %0, %1, %2;" : "=r"(r) : "f"(hi), "f"(lo));
    return r;
}

// ---------------------------------------------------------------------------
// fp32 -> (bf16 hi, bf16 lo) split (flat layout)
// ---------------------------------------------------------------------------
__global__ __launch_bounds__(256) void split_kernel(
    const float* __restrict__ src, __nv_bfloat16* __restrict__ hi,
    __nv_bfloat16* __restrict__ lo, int n)
{
    int i4 = (blockIdx.x * blockDim.x + threadIdx.x) * 4;
    if (i4 >= n) return;
    float4 v = *(const float4*)(src + i4);
    __nv_bfloat16 h0 = __float2bfloat16(v.x);
    __nv_bfloat16 h1 = __float2bfloat16(v.y);
    __nv_bfloat16 h2 = __float2bfloat16(v.z);
    __nv_bfloat16 h3 = __float2bfloat16(v.w);
    __nv_bfloat16 l0 = __float2bfloat16(v.x - __bfloat162float(h0));
    __nv_bfloat16 l1 = __float2bfloat16(v.y - __bfloat162float(h1));
    __nv_bfloat16 l2 = __float2bfloat16(v.z - __bfloat162float(h2));
    __nv_bfloat16 l3 = __float2bfloat16(v.w - __bfloat162float(h3));
    reinterpret_cast<__nv_bfloat162*>(hi + i4)[0] = __nv_bfloat162(h0, h1);
    reinterpret_cast<__nv_bfloat162*>(hi + i4)[1] = __nv_bfloat162(h2, h3);
    reinterpret_cast<__nv_bfloat162*>(lo + i4)[0] = __nv_bfloat162(l0, l1);
    reinterpret_cast<__nv_bfloat162*>(lo + i4)[1] = __nv_bfloat162(l2, l3);
}

// V: token-major fp32 -> head-major bf16 hi/lo
__global__ __launch_bounds__(256) void split_v_kernel() {
    int i4 = (blockIdx.x * blockDim.x + threadIdx.x) * 4;
    if (i4 >= NTOK * D_) return;
    int token = i4 >> 10;
    int rem = i4 & 1023;
    int h = rem >> 6, c = rem & 63;
    int b = token >> 11, t = token & (T_ - 1);
    size_t oi = (((size_t)(b * H_ + h)) * T_ + t) * HD_ + c;
    float4 v = *(const float4*)(g_v + i4);
    __nv_bfloat16 h0 = __float2bfloat16(v.x);
    __nv_bfloat16 h1 = __float2bfloat16(v.y);
    __nv_bfloat16 h2 = __float2bfloat16(v.z);
    __nv_bfloat16 h3 = __float2bfloat16(v.w);
    reinterpret_cast<__nv_bfloat162*>(g_vhi + oi)[0] = __nv_bfloat162(h0, h1);
    reinterpret_cast<__nv_bfloat162*>(g_vhi + oi)[1] = __nv_bfloat162(h2, h3);
    reinterpret_cast<__nv_bfloat162*>(g_vlo + oi)[0] = __nv_bfloat162(
        __float2bfloat16(v.x - __bfloat162float(h0)),
        __float2bfloat16(v.y - __bfloat162float(h1)));
    reinterpret_cast<__nv_bfloat162*>(g_vlo + oi)[1] = __nv_bfloat162(
        __float2bfloat16(v.z - __bfloat162float(h2)),
        __float2bfloat16(v.w - __bfloat162float(h3)));
}

// ---------------------------------------------------------------------------
// mma.sync GEMM, bf16x3 split: C[8192,1024] = A @ W^T
// CTA tile 256x128, 8 warps (4x2) with 64x64 warp tiles, BK=32,
// 3-stage cp.async ring, one __syncthreads per chunk.
// grid.z selects weight/output (QKV fused in one launch).
// ---------------------------------------------------------------------------
#define GM_ROWB   80
#define GM_A_ARR  (256 * GM_ROWB)               // 20480
#define GM_B_ARR  (128 * GM_ROWB)               // 10240
#define GM_STAGE  (2 * GM_A_ARR + 2 * GM_B_ARR) // 61440
#define GM_SMEM   (3 * GM_STAGE)                // 184320
#define GM_CHUNKS 32

__device__ __forceinline__ void gm_load_stage(
    uint32_t sbase, const __nv_bfloat16* a_hi, const __nv_bfloat16* a_lo,
    const __nv_bfloat16* b_hi, const __nv_bfloat16* b_lo, int k0, int tid)
{
    int seg = tid & 3;            // 16B segment within 64B row
    int r0  = tid >> 2;           // 0..63
    const __nv_bfloat16* ah = a_hi + k0 + seg * 8;
    const __nv_bfloat16* al = a_lo + k0 + seg * 8;
    const __nv_bfloat16* bh = b_hi + k0 + seg * 8;
    const __nv_bfloat16* bl = b_lo + k0 + seg * 8;
    uint32_t d0 = sbase + seg * 16;
#pragma unroll
    for (int rr = 0; rr < 4; rr++) {
        int row = r0 + rr * 64;
        cp_async16(d0 + row * GM_ROWB, ah + (size_t)row * D_);
        cp_async16(d0 + GM_A_ARR + row * GM_ROWB, al + (size_t)row * D_);
    }
#pragma unroll
    for (int rr = 0; rr < 2; rr++) {
        int row = r0 + rr * 64;
        cp_async16(d0 + 2 * GM_A_ARR + row * GM_ROWB, bh + (size_t)row * D_);
        cp_async16(d0 + 2 * GM_A_ARR + GM_B_ARR + row * GM_ROWB, bl + (size_t)row * D_);
    }
}

__global__ __launch_bounds__(256, 1) void gemm_mma_kernel(
    const __nv_bfloat16* __restrict__ Ahi, const __nv_bfloat16* __restrict__ Alo,
    const __nv_bfloat16* __restrict__ Whi, const __nv_bfloat16* __restrict__ Wlo,
    int wbase, float* C0, float* C1, float* C2)
{
    extern __shared__ __align__(128) char smem[];
    uint32_t sb = smem_to_u32(smem);

    const int tid  = threadIdx.x;
    const int wid  = tid >> 5;
    const int lane = tid & 31;
    const int wm = wid & 3;       // 4 warp rows of 64
    const int wn = wid >> 2;      // 2 warp cols of 64
    const int bm = blockIdx.y * 256;
    const int bn = blockIdx.x * 128;
    const int z  = blockIdx.z;

    float* C = (z == 0) ? C0 : (z == 1) ? C1 : C2;
    const __nv_bfloat16* a_hi = Ahi + (size_t)bm * D_;
    const __nv_bfloat16* a_lo = Alo + (size_t)bm * D_;
    const __nv_bfloat16* b_hi = Whi + (size_t)(wbase + z) * D_ * D_ + (size_t)bn * D_;
    const __nv_bfloat16* b_lo = Wlo + (size_t)(wbase + z) * D_ * D_ + (size_t)bn * D_;

    float c[4][8][4];
#pragma unroll
    for (int mt = 0; mt < 4; mt++)
#pragma unroll
        for (int nt = 0; nt < 8; nt++)
#pragma unroll
            for (int r = 0; r < 4; r++) c[mt][nt][r] = 0.0f;

    // ldmatrix lane addressing
    const int rowA = lane & 15;
    const int kbA  = lane >> 4;
    const int rowB = (lane & 7) + ((lane >> 4) << 3);
    const int kbB  = (lane >> 3) & 1;
    const uint32_t aoff = (uint32_t)(wm * 64 + rowA) * GM_ROWB + kbA * 16;
    const uint32_t boff = (uint32_t)(wn * 64 + rowB) * GM_ROWB + kbB * 16;

    // prologue: 2 stages in flight
    gm_load_stage(sb, a_hi, a_lo, b_hi, b_lo, 0, tid);
    cp_commit();
    gm_load_stage(sb + GM_STAGE, a_hi, a_lo, b_hi, b_lo, 32, tid);
    cp_commit();

    int stage = 0;
    for (int i = 0; i < GM_CHUNKS; i++) {
        if (i < GM_CHUNKS - 1) cp_wait<1>(); else cp_wait<0>();
        __syncthreads();
        if (i + 2 < GM_CHUNKS) {
            int ns = (stage + 2 >= 3) ? stage - 1 : stage + 2;
            gm_load_stage(sb + ns * GM_STAGE, a_hi, a_lo, b_hi, b_lo, (i + 2) * 32, tid);
            cp_commit();
        }
        uint32_t st = sb + stage * GM_STAGE;

#pragma unroll
        for (int ks = 0; ks < 2; ks++) {
            uint32_t koff = ks * 32;
            uint32_t fah[4][4], fal[4][4];
#pragma unroll
            for (int mt = 0; mt < 4; mt++) {
                ldsm_x4(fah[mt], st + aoff + koff + mt * 16 * GM_ROWB);
                ldsm_x4(fal[mt], st + GM_A_ARR + aoff + koff + mt * 16 * GM_ROWB);
            }
#pragma unroll
            for (int np = 0; np < 4; np++) {
                uint32_t fbh[4], fbl[4];
                ldsm_x4(fbh, st + 2 * GM_A_ARR + boff + koff + np * 16 * GM_ROWB);
                ldsm_x4(fbl, st + 2 * GM_A_ARR + GM_B_ARR + boff + koff + np * 16 * GM_ROWB);
#pragma unroll
                for (int mt = 0; mt < 4; mt++) {
#pragma unroll
                    for (int half = 0; half < 2; half++) {
                        float* cc = c[mt][np * 2 + half];
                        mma_bf16(cc, fah[mt], fbh + half * 2);
                        mma_bf16(cc, fal[mt], fbh + half * 2);
                        mma_bf16(cc, fah[mt], fbl + half * 2);
                    }
                }
            }
        }
        stage = (stage + 1 >= 3) ? 0 : stage + 1;
    }

    // epilogue: direct fp32 global stores
    const int erow = bm + wm * 64 + (lane >> 2);
    const int ecol = bn + wn * 64 + (lane & 3) * 2;
#pragma unroll
    for (int mt = 0; mt < 4; mt++)
#pragma unroll
        for (int nt = 0; nt < 8; nt++) {
            int r0 = erow + mt * 16;
            int cc = ecol + (nt >> 1) * 16 + (nt & 1) * 8;
            *(float2*)&C[(size_t)r0 * D_ + cc]       = make_float2(c[mt][nt][0], c[mt][nt][1]);
            *(float2*)&C[(size_t)(r0 + 8) * D_ + cc] = make_float2(c[mt][nt][2], c[mt][nt][3]);
        }
}

// ---------------------------------------------------------------------------
// RoPE tables in fp64 (fast-math cosf unsafe at theta ~ 2048 rad)
// ---------------------------------------------------------------------------
__global__ void rope_tables_kernel() {
    int i = blockIdx.x * blockDim.x + threadIdx.x;
    if (i >= T_ * 32) return;
    int t = i >> 5;
    int j = i & 31;
    float f32 = 0.0f;
    if (j < 16) f32 = (float)pow(1.0 / 1024.0, (double)j / 15.0);
    float theta = (float)t * f32;
    g_cos[i] = (float)cos((double)theta);
    g_sin[i] = (float)sin((double)theta);
}

// ---------------------------------------------------------------------------
// Fused per-head RMSNorm + RoPE; writes head-major bf16 hi/lo.
// Q additionally scaled by 1/sqrt(HD) = 0.125.
// ---------------------------------------------------------------------------
__global__ __launch_bounds__(256) void norm_rope_kernel() {
    int gw   = (blockIdx.x * blockDim.x + threadIdx.x) >> 5;
    int lane = threadIdx.x & 31;
    if (gw >= NTOK * H_) return;

    int token = gw >> 4;
    int h = gw & 15;
    int b = token >> 11;
    int t = token & (T_ - 1);
    size_t base = (size_t)gw * 64;
    size_t hb = (((size_t)(b * H_ + h)) * T_ + t) * HD_;

    float c = g_cos[t * 32 + lane];
    float s = g_sin[t * 32 + lane];

    {   // Q (scaled by 0.125)
        float a  = g_q[base + lane];
        float b2 = g_q[base + lane + 32];
        float ss = a * a + b2 * b2;
#pragma unroll
        for (int m = 16; m > 0; m >>= 1) ss += __shfl_xor_sync(0xffffffffu, ss, m);
        float r = rsqrtf(ss * (1.0f / 64.0f) + 1e-6f);
        a *= r; b2 *= r;
        float y1 = (a * c + b2 * s) * 0.125f;
        float y2 = (-a * s + b2 * c) * 0.125f;
        __nv_bfloat16 h1 = __float2bfloat16(y1);
        __nv_bfloat16 h2 = __float2bfloat16(y2);
        g_qhi[hb + lane]      = h1;
        g_qhi[hb + lane + 32] = h2;
        g_qlo[hb + lane]      = __float2bfloat16(y1 - __bfloat162float(h1));
        g_qlo[hb + lane + 32] = __float2bfloat16(y2 - __bfloat162float(h2));
    }
    {   // K
        float a  = g_k[base + lane];
        float b2 = g_k[base + lane + 32];
        float ss = a * a + b2 * b2;
#pragma unroll
        for (int m = 16; m > 0; m >>= 1) ss += __shfl_xor_sync(0xffffffffu, ss, m);
        float r = rsqrtf(ss * (1.0f / 64.0f) + 1e-6f);
        a *= r; b2 *= r;
        float y1 = a * c + b2 * s;
        float y2 = -a * s + b2 * c;
        __nv_bfloat16 h1 = __float2bfloat16(y1);
        __nv_bfloat16 h2 = __float2bfloat16(y2);
        g_khi[hb + lane]      = h1;
        g_khi[hb + lane + 32] = h2;
        g_klo[hb + lane]      = __float2bfloat16(y1 - __bfloat162float(h1));
        g_klo[hb + lane + 32] = __float2bfloat16(y2 - __bfloat162float(h2));
    }
}

// ---------------------------------------------------------------------------
// Flash attention via mma.sync, bf16x3 (causal). Unchanged from R4.
// ---------------------------------------------------------------------------
#define FROWB   144u
#define FQ_SIZE (128 * 144)
#define FKV_OFF (2 * FQ_SIZE)
#define FKV_ARR (64 * 144)
#define FSTAGE  (4 * FKV_ARR)
#define FMMA_SMEM (FKV_OFF + 2 * FSTAGE)

__device__ __forceinline__ void f_load_kv(
    uint32_t dst, const __nv_bfloat16* kh, const __nv_bfloat16* kl,
    const __nv_bfloat16* vh, const __nv_bfloat16* vl, size_t goff, int tid)
{
    const __nv_bfloat16* srcs[4] = {kh, kl, vh, vl};
    int seg = tid & 7, r0 = tid >> 3;
#pragma unroll
    for (int arr = 0; arr < 4; arr++) {
        const __nv_bfloat16* s = srcs[arr] + goff + seg * 8;
        uint32_t d = dst + arr * FKV_ARR + seg * 16;
#pragma unroll
        for (int rr = 0; rr < 2; rr++) {
            int row = r0 + rr * 32;
            cp_async16(d + row * FROWB, s + row * HD_);
        }
    }
}

__global__ __launch_bounds__(256, 1) void flash_mma_kernel(
    const __nv_bfloat16* __restrict__ Qhi, const __nv_bfloat16* __restrict__ Qlo,
    const __nv_bfloat16* __restrict__ Khi, const __nv_bfloat16* __restrict__ Klo,
    const __nv_bfloat16* __restrict__ Vhi, const __nv_bfloat16* __restrict__ Vlo,
    float* __restrict__ O)
{
    extern __shared__ __align__(128) char fsm[];
    uint32_t sb = smem_to_u32(fsm);
    const int tid = threadIdx.x, wid = tid >> 5, lane = tid & 31;
    const int bh = blockIdx.x;
    const int qt = 15 - blockIdx.y;
    const int b = bh >> 4, h = bh & 15;
    const size_t headoff = (size_t)bh * T_ * HD_;
    const int nkt = 2 * qt + 2;

    {
        int seg = tid & 7, r0 = tid >> 3;
        const __nv_bfloat16* q0 = Qhi + headoff + (size_t)qt * 128 * HD_ + seg * 8;
        const __nv_bfloat16* q1 = Qlo + headoff + (size_t)qt * 128 * HD_ + seg * 8;
#pragma unroll
        for (int rr = 0; rr < 4; rr++) {
            int row = r0 + rr * 32;
            cp_async16(sb + row * FROWB + seg * 16, q0 + row * HD_);
            cp_async16(sb + FQ_SIZE + row * FROWB + seg * 16, q1 + row * HD_);
        }
    }
    f_load_kv(sb + FKV_OFF, Khi, Klo, Vhi, Vlo, headoff, tid);
    cp_commit();

    uint32_t fqh[4][4], fql[4][4];
    float o[8][4];
#pragma unroll
    for (int nt = 0; nt < 8; nt++)
#pragma unroll
        for (int r = 0; r < 4; r++) o[nt][r] = 0.0f;
    float m0 = -1e30f, m1 = -1e30f, l0 = 0.0f, l1 = 0.0f;

    const uint32_t qrow_off = (uint32_t)(wid * 16 + (lane & 15)) * FROWB + (lane >> 4) * 16;
    const uint32_t krow_off = (uint32_t)((lane & 7) + ((lane >> 4) << 3)) * FROWB
                              + ((lane >> 3) & 1) * 16;
    const uint32_t vrow_off = (uint32_t)(lane & 15) * FROWB + (lane >> 4) * 16;

    for (int jt = 0; jt < nkt; jt++) {
        if (jt + 1 < nkt) {
            f_load_kv(sb + FKV_OFF + ((jt + 1) & 1) * FSTAGE, Khi, Klo, Vhi, Vlo,
                      headoff + (size_t)(jt + 1) * 64 * HD_, tid);
            cp_commit();
            cp_wait<1>();
        } else {
            cp_wait<0>();
        }
        __syncthreads();

        if (jt == 0) {
#pragma unroll
            for (int ks = 0; ks < 4; ks++) {
                ldsm_x4(fqh[ks], sb + qrow_off + ks * 32);
                ldsm_x4(fql[ks], sb + FQ_SIZE + qrow_off + ks * 32);
            }
        }

        uint32_t st = sb + FKV_OFF + (jt & 1) * FSTAGE;

        float s[8][4];
#pragma unroll
        for (int nt = 0; nt < 8; nt++)
#pragma unroll
            for (int r = 0; r < 4; r++) s[nt][r] = 0.0f;

#pragma unroll
        for (int np = 0; np < 4; np++) {
#pragma unroll
            for (int ks = 0; ks < 4; ks++) {
                uint32_t addr = st + krow_off + np * 16 * FROWB + ks * 32;
                uint32_t fk[4];
                ldsm_x4(fk, addr);
                mma_bf16(s[2 * np],     fqh[ks], fk + 0);
                mma_bf16(s[2 * np + 1], fqh[ks], fk + 2);
                mma_bf16(s[2 * np],     fql[ks], fk + 0);
                mma_bf16(s[2 * np + 1], fql[ks], fk + 2);
                ldsm_x4(fk, addr + FKV_ARR);
                mma_bf16(s[2 * np],     fqh[ks], fk + 0);
                mma_bf16(s[2 * np + 1], fqh[ks], fk + 2);
            }
        }

        if (jt >= 2 * qt) {
            int grow = qt * 128 + wid * 16 + (lane >> 2);
            int gc0 = jt * 64 + (lane & 3) * 2;
#pragma unroll
            for (int nt = 0; nt < 8; nt++) {
                int cc = gc0 + nt * 8;
                if (cc > grow)          s[nt][0] = -1e30f;
                if (cc + 1 > grow)      s[nt][1] = -1e30f;
                if (cc > grow + 8)      s[nt][2] = -1e30f;
                if (cc + 1 > grow + 8)  s[nt][3] = -1e30f;
            }
        }

        float mx0 = -1e30f, mx1 = -1e30f;
#pragma unroll
        for (int nt = 0; nt < 8; nt++) {
            mx0 = fmaxf(mx0, fmaxf(s[nt][0], s[nt][1]));
            mx1 = fmaxf(mx1, fmaxf(s[nt][2], s[nt][3]));
        }
        mx0 = fmaxf(mx0, __shfl_xor_sync(0xffffffffu, mx0, 1));
        mx0 = fmaxf(mx0, __shfl_xor_sync(0xffffffffu, mx0, 2));
        mx1 = fmaxf(mx1, __shfl_xor_sync(0xffffffffu, mx1, 1));
        mx1 = fmaxf(mx1, __shfl_xor_sync(0xffffffffu, mx1, 2));
        float mn0 = fmaxf(m0, mx0), mn1 = fmaxf(m1, mx1);
        float al0 = __expf(m0 - mn0), al1 = __expf(m1 - mn1);
        float rs0 = 0.0f, rs1 = 0.0f;
#pragma unroll
        for (int nt = 0; nt < 8; nt++) {
            s[nt][0] = __expf(s[nt][0] - mn0);
            s[nt][1] = __expf(s[nt][1] - mn0);
            s[nt][2] = __expf(s[nt][2] - mn1);
            s[nt][3] = __expf(s[nt][3] - mn1);
            rs0 += s[nt][0] + s[nt][1];
            rs1 += s[nt][2] + s[nt][3];
        }
        rs0 += __shfl_xor_sync(0xffffffffu, rs0, 1);
        rs0 += __shfl_xor_sync(0xffffffffu, rs0, 2);
        rs1 += __shfl_xor_sync(0xffffffffu, rs1, 1);
        rs1 += __shfl_xor_sync(0xffffffffu, rs1, 2);
        l0 = l0 * al0 + rs0; m0 = mn0;
        l1 = l1 * al1 + rs1; m1 = mn1;
#pragma unroll
        for (int nt = 0; nt < 8; nt++) {
            o[nt][0] *= al0; o[nt][1] *= al0;
            o[nt][2] *= al1; o[nt][3] *= al1;
        }

        uint32_t fph[4][4], fpl[4][4];
#pragma unroll
        for (int f = 0; f < 4; f++) {
#pragma unroll
            for (int half = 0; half < 2; half++) {
                int nt = 2 * f + half;
#pragma unroll
                for (int rh = 0; rh < 2; rh++) {
                    float p0 = s[nt][rh * 2], p1 = s[nt][rh * 2 + 1];
                    uint32_t hi = pack_bf16x2(p0, p1);
                    float h0 = __uint_as_float(hi << 16);
                    float h1 = __uint_as_float(hi & 0xFFFF0000u);
                    uint32_t lo = pack_bf16x2(p0 - h0, p1 - h1);
                    fph[f][half * 2 + rh] = hi;
                    fpl[f][half * 2 + rh] = lo;
                }
            }
        }

#pragma unroll
        for (int nh = 0; nh < 4; nh++) {
#pragma unroll
            for (int ks = 0; ks < 4; ks++) {
                uint32_t addr = st + 2 * FKV_ARR + vrow_off + ks * 16 * FROWB + nh * 32;
                uint32_t fv[4];
                ldsm_x4_t(fv, addr);
                mma_bf16(o[2 * nh],     fph[ks], fv + 0);
                mma_bf16(o[2 * nh + 1], fph[ks], fv + 2);
                mma_bf16(o[2 * nh],     fpl[ks], fv + 0);
                mma_bf16(o[2 * nh + 1], fpl[ks], fv + 2);
                ldsm_x4_t(fv, addr + FKV_ARR);
                mma_bf16(o[2 * nh],     fph[ks], fv + 0);
                mma_bf16(o[2 * nh + 1], fph[ks], fv + 2);
            }
        }
        __syncthreads();
    }

    float inv0 = 1.0f / l0, inv1 = 1.0f / l1;
    int row = qt * 128 + wid * 16 + (lane >> 2);
    float* op0 = O + ((size_t)b * T_ + row) * D_ + h * 64 + (lane & 3) * 2;
    float* op1 = op0 + 8 * D_;
#pragma unroll
    for (int nt = 0; nt < 8; nt++) {
        *(float2*)(op0 + nt * 8) = make_float2(o[nt][0] * inv0, o[nt][1] * inv0);
        *(float2*)(op1 + nt * 8) = make_float2(o[nt][2] * inv1, o[nt][3] * inv1);
    }
}

// ---------------------------------------------------------------------------
// Launch
// ---------------------------------------------------------------------------
extern "C" void kernel_launch(void* const* d_in, const int* in_sizes, int n_in,
                              void* d_out, int out_size)
{
    (void)in_sizes; (void)n_in; (void)out_size;
    const float* x  = (const float*)d_in[0];
    const float* w[4] = {(const float*)d_in[1], (const float*)d_in[2],
                         (const float*)d_in[3], (const float*)d_in[4]};
    float* out = (float*)d_out;

    float *qp, *kp, *vp, *op;
    __nv_bfloat16 *ahi, *alo, *whi, *wlo;
    __nv_bfloat16 *qhi, *qlo, *khi, *klo, *vhi, *vlo;
    cudaGetSymbolAddress((void**)&qp, g_q);
    cudaGetSymbolAddress((void**)&kp, g_k);
    cudaGetSymbolAddress((void**)&vp, g_v);
    cudaGetSymbolAddress((void**)&op, g_o);
    cudaGetSymbolAddress((void**)&ahi, g_ahi);
    cudaGetSymbolAddress((void**)&alo, g_alo);
    cudaGetSymbolAddress((void**)&whi, g_whi);
    cudaGetSymbolAddress((void**)&wlo, g_wlo);
    cudaGetSymbolAddress((void**)&qhi, g_qhi);
    cudaGetSymbolAddress((void**)&qlo, g_qlo);
    cudaGetSymbolAddress((void**)&khi, g_khi);
    cudaGetSymbolAddress((void**)&klo, g_klo);
    cudaGetSymbolAddress((void**)&vhi, g_vhi);
    cudaGetSymbolAddress((void**)&vlo, g_vlo);

    cudaFuncSetAttribute(gemm_mma_kernel,
                         cudaFuncAttributeMaxDynamicSharedMemorySize, GM_SMEM);
    cudaFuncSetAttribute(flash_mma_kernel,
                         cudaFuncAttributeMaxDynamicSharedMemorySize, FMMA_SMEM);

    rope_tables_kernel<<<(T_ * 32 + 255) / 256, 256>>>();

    split_kernel<<<(NTOK * D_ / 4 + 255) / 256, 256>>>(x, ahi, alo, NTOK * D_);
    for (int i = 0; i < 4; i++)
        split_kernel<<<(D_ * D_ / 4 + 255) / 256, 256>>>(
            w[i], whi + (size_t)i * D_ * D_, wlo + (size_t)i * D_ * D_, D_ * D_);

    // fused Q/K/V projections: grid.z = 3
    gemm_mma_kernel<<<dim3(D_ / 128, NTOK / 256, 3), 256, GM_SMEM>>>(
        ahi, alo, whi, wlo, 0, qp, kp, vp);

    norm_rope_kernel<<<(NTOK * H_) / 8, 256>>>();
    split_v_kernel<<<(NTOK * D_ / 4 + 255) / 256, 256>>>();

    flash_mma_kernel<<<dim3(BH_, T_ / 128), 256, FMMA_SMEM>>>(
        qhi, qlo, khi, klo, vhi, vlo, op);

    split_kernel<<<(NTOK * D_ / 4 + 255) / 256, 256>>>(op, ahi, alo, NTOK * D_);
    gemm_mma_kernel<<<dim3(D_ / 128, NTOK / 256, 1), 256, GM_SMEM>>>(
        ahi, alo, whi, wlo, 3, out, out, out);
}

// round 6
// speedup vs baseline: 2.8214x; 1.0299x over previous
#include <cuda_runtime.h>
#include <cuda_bf16.h>
#include <math.h>
#include <stdint.h>

// Problem constants
#define B_   4
#define T_   2048
#define D_   1024
#define H_   16
#define HD_  64
#define NTOK (B_ * T_)   // 8192
#define BH_  (B_ * H_)   // 64

// ---------------------------------------------------------------------------
// Scratch (device globals: allocation-free rule)
// ---------------------------------------------------------------------------
__device__ float g_q[NTOK * D_];
__device__ float g_k[NTOK * D_];
__device__ float g_v[NTOK * D_];
__device__ float g_o[NTOK * D_];
__device__ float g_cos[T_ * 32];
__device__ float g_sin[T_ * 32];
__device__ float g_freqf[16];

// bf16 hi/lo splits for projection GEMMs
__device__ __nv_bfloat16 g_ahi[NTOK * D_];
__device__ __nv_bfloat16 g_alo[NTOK * D_];
__device__ __nv_bfloat16 g_whi[4][D_ * D_];
__device__ __nv_bfloat16 g_wlo[4][D_ * D_];

// head-major bf16 hi/lo for flash attention: [bh][T][HD]
__device__ __nv_bfloat16 g_qhi[BH_ * T_ * HD_];
__device__ __nv_bfloat16 g_qlo[BH_ * T_ * HD_];
__device__ __nv_bfloat16 g_khi[BH_ * T_ * HD_];
__device__ __nv_bfloat16 g_klo[BH_ * T_ * HD_];
__device__ __nv_bfloat16 g_vhi[BH_ * T_ * HD_];
__device__ __nv_bfloat16 g_vlo[BH_ * T_ * HD_];

// ---------------------------------------------------------------------------
// PTX helpers (base compute_103 target: mma.sync / ldmatrix / cp.async only)
// ---------------------------------------------------------------------------
__device__ __forceinline__ uint32_t smem_to_u32(const void* p) {
    uint32_t a;
    asm("{ .reg .u64 t; cvta.to.shared.u64 t, %1; cvt.u32.u64 %0, t; }"
        : "=r"(a) : "l"(p));
    return a;
}

__device__ __forceinline__ void ldsm_x4(uint32_t* r, uint32_t addr) {
    asm volatile("ldmatrix.sync.aligned.m8n8.x4.shared.b16 {%0,%1,%2,%3}, [%4];"
                 : "=r"(r[0]), "=r"(r[1]), "=r"(r[2]), "=r"(r[3]) : "r"(addr));
}

__device__ __forceinline__ void ldsm_x4_t(uint32_t* r, uint32_t addr) {
    asm volatile("ldmatrix.sync.aligned.m8n8.x4.trans.shared.b16 {%0,%1,%2,%3}, [%4];"
                 : "=r"(r[0]), "=r"(r[1]), "=r"(r[2]), "=r"(r[3]) : "r"(addr));
}

__device__ __forceinline__ void mma_bf16(float* c, const uint32_t* a, const uint32_t* b) {
    asm volatile(
        "mma.sync.aligned.m16n8k16.row.col.f32.bf16.bf16.f32 "
        "{%0,%1,%2,%3}, {%4,%5,%6,%7}, {%8,%9}, {%0,%1,%2,%3};"
        : "+f"(c[0]), "+f"(c[1]), "+f"(c[2]), "+f"(c[3])
        : "r"(a[0]), "r"(a[1]), "r"(a[2]), "r"(a[3]), "r"(b[0]), "r"(b[1]));
}

__device__ __forceinline__ void cp_async16(uint32_t dst, const void* src) {
    asm volatile("cp.async.cg.shared.global [%0], [%1], 16;"
                 :: "r"(dst), "l"(src));
}
__device__ __forceinline__ void cp_commit() {
    asm volatile("cp.async.commit_group;" ::: "memory");
}
template <int N>
__device__ __forceinline__ void cp_wait() {
    asm volatile("cp.async.wait_group %0;" :: "n"(N) : "memory");
}

__device__ __forceinline__ uint32_t pack_bf16x2(float lo, float hi) {
    uint32_t r;
    asm("cvt.rn.bf16x2.f32 %0, %1, %2;" : "=r"(r) : "f"(hi), "f"(lo));
    return r;
}

// ---------------------------------------------------------------------------
// fp32 -> (bf16 hi, bf16 lo) split (flat layout)
// ---------------------------------------------------------------------------
__global__ __launch_bounds__(256) void split_kernel(
    const float* __restrict__ src, __nv_bfloat16* __restrict__ hi,
    __nv_bfloat16* __restrict__ lo, int n)
{
    int i4 = (blockIdx.x * blockDim.x + threadIdx.x) * 4;
    if (i4 >= n) return;
    float4 v = *(const float4*)(src + i4);
    __nv_bfloat16 h0 = __float2bfloat16(v.x);
    __nv_bfloat16 h1 = __float2bfloat16(v.y);
    __nv_bfloat16 h2 = __float2bfloat16(v.z);
    __nv_bfloat16 h3 = __float2bfloat16(v.w);
    __nv_bfloat16 l0 = __float2bfloat16(v.x - __bfloat162float(h0));
    __nv_bfloat16 l1 = __float2bfloat16(v.y - __bfloat162float(h1));
    __nv_bfloat16 l2 = __float2bfloat16(v.z - __bfloat162float(h2));
    __nv_bfloat16 l3 = __float2bfloat16(v.w - __bfloat162float(h3));
    reinterpret_cast<__nv_bfloat162*>(hi + i4)[0] = __nv_bfloat162(h0, h1);
    reinterpret_cast<__nv_bfloat162*>(hi + i4)[1] = __nv_bfloat162(h2, h3);
    reinterpret_cast<__nv_bfloat162*>(lo + i4)[0] = __nv_bfloat162(l0, l1);
    reinterpret_cast<__nv_bfloat162*>(lo + i4)[1] = __nv_bfloat162(l2, l3);
}

// All 4 weights in one launch (dst g_whi/g_wlo are contiguous [4][D*D])
__global__ __launch_bounds__(256) void split_w_kernel(
    const float* __restrict__ w0, const float* __restrict__ w1,
    const float* __restrict__ w2, const float* __restrict__ w3,
    __nv_bfloat16* __restrict__ hi, __nv_bfloat16* __restrict__ lo)
{
    int i4 = (blockIdx.x * blockDim.x + threadIdx.x) * 4;
    if (i4 >= 4 * D_ * D_) return;
    int wi = i4 >> 20;                 // D*D = 2^20
    int off = i4 & (D_ * D_ - 1);
    const float* src = (wi == 0) ? w0 : (wi == 1) ? w1 : (wi == 2) ? w2 : w3;
    float4 v = *(const float4*)(src + off);
    __nv_bfloat16 h0 = __float2bfloat16(v.x);
    __nv_bfloat16 h1 = __float2bfloat16(v.y);
    __nv_bfloat16 h2 = __float2bfloat16(v.z);
    __nv_bfloat16 h3 = __float2bfloat16(v.w);
    reinterpret_cast<__nv_bfloat162*>(hi + i4)[0] = __nv_bfloat162(h0, h1);
    reinterpret_cast<__nv_bfloat162*>(hi + i4)[1] = __nv_bfloat162(h2, h3);
    reinterpret_cast<__nv_bfloat162*>(lo + i4)[0] = __nv_bfloat162(
        __float2bfloat16(v.x - __bfloat162float(h0)),
        __float2bfloat16(v.y - __bfloat162float(h1)));
    reinterpret_cast<__nv_bfloat162*>(lo + i4)[1] = __nv_bfloat162(
        __float2bfloat16(v.z - __bfloat162float(h2)),
        __float2bfloat16(v.w - __bfloat162float(h3)));
}

// V: token-major fp32 -> head-major bf16 hi/lo
__global__ __launch_bounds__(256) void split_v_kernel() {
    int i4 = (blockIdx.x * blockDim.x + threadIdx.x) * 4;
    if (i4 >= NTOK * D_) return;
    int token = i4 >> 10;
    int rem = i4 & 1023;
    int h = rem >> 6, c = rem & 63;
    int b = token >> 11, t = token & (T_ - 1);
    size_t oi = (((size_t)(b * H_ + h)) * T_ + t) * HD_ + c;
    float4 v = *(const float4*)(g_v + i4);
    __nv_bfloat16 h0 = __float2bfloat16(v.x);
    __nv_bfloat16 h1 = __float2bfloat16(v.y);
    __nv_bfloat16 h2 = __float2bfloat16(v.z);
    __nv_bfloat16 h3 = __float2bfloat16(v.w);
    reinterpret_cast<__nv_bfloat162*>(g_vhi + oi)[0] = __nv_bfloat162(h0, h1);
    reinterpret_cast<__nv_bfloat162*>(g_vhi + oi)[1] = __nv_bfloat162(h2, h3);
    reinterpret_cast<__nv_bfloat162*>(g_vlo + oi)[0] = __nv_bfloat162(
        __float2bfloat16(v.x - __bfloat162float(h0)),
        __float2bfloat16(v.y - __bfloat162float(h1)));
    reinterpret_cast<__nv_bfloat162*>(g_vlo + oi)[1] = __nv_bfloat162(
        __float2bfloat16(v.z - __bfloat162float(h2)),
        __float2bfloat16(v.w - __bfloat162float(h3)));
}

// ---------------------------------------------------------------------------
// mma.sync GEMM, bf16x3 split (unchanged from R5)
// ---------------------------------------------------------------------------
#define GM_ROWB   80
#define GM_A_ARR  (256 * GM_ROWB)
#define GM_B_ARR  (128 * GM_ROWB)
#define GM_STAGE  (2 * GM_A_ARR + 2 * GM_B_ARR)
#define GM_SMEM   (3 * GM_STAGE)
#define GM_CHUNKS 32

__device__ __forceinline__ void gm_load_stage(
    uint32_t sbase, const __nv_bfloat16* a_hi, const __nv_bfloat16* a_lo,
    const __nv_bfloat16* b_hi, const __nv_bfloat16* b_lo, int k0, int tid)
{
    int seg = tid & 3;
    int r0  = tid >> 2;
    const __nv_bfloat16* ah = a_hi + k0 + seg * 8;
    const __nv_bfloat16* al = a_lo + k0 + seg * 8;
    const __nv_bfloat16* bh = b_hi + k0 + seg * 8;
    const __nv_bfloat16* bl = b_lo + k0 + seg * 8;
    uint32_t d0 = sbase + seg * 16;
#pragma unroll
    for (int rr = 0; rr < 4; rr++) {
        int row = r0 + rr * 64;
        cp_async16(d0 + row * GM_ROWB, ah + (size_t)row * D_);
        cp_async16(d0 + GM_A_ARR + row * GM_ROWB, al + (size_t)row * D_);
    }
#pragma unroll
    for (int rr = 0; rr < 2; rr++) {
        int row = r0 + rr * 64;
        cp_async16(d0 + 2 * GM_A_ARR + row * GM_ROWB, bh + (size_t)row * D_);
        cp_async16(d0 + 2 * GM_A_ARR + GM_B_ARR + row * GM_ROWB, bl + (size_t)row * D_);
    }
}

__global__ __launch_bounds__(256, 1) void gemm_mma_kernel(
    const __nv_bfloat16* __restrict__ Ahi, const __nv_bfloat16* __restrict__ Alo,
    const __nv_bfloat16* __restrict__ Whi, const __nv_bfloat16* __restrict__ Wlo,
    int wbase, float* C0, float* C1, float* C2)
{
    extern __shared__ __align__(128) char smem[];
    uint32_t sb = smem_to_u32(smem);

    const int tid  = threadIdx.x;
    const int wid  = tid >> 5;
    const int lane = tid & 31;
    const int wm = wid & 3;
    const int wn = wid >> 2;
    const int bm = blockIdx.y * 256;
    const int bn = blockIdx.x * 128;
    const int z  = blockIdx.z;

    float* C = (z == 0) ? C0 : (z == 1) ? C1 : C2;
    const __nv_bfloat16* a_hi = Ahi + (size_t)bm * D_;
    const __nv_bfloat16* a_lo = Alo + (size_t)bm * D_;
    const __nv_bfloat16* b_hi = Whi + (size_t)(wbase + z) * D_ * D_ + (size_t)bn * D_;
    const __nv_bfloat16* b_lo = Wlo + (size_t)(wbase + z) * D_ * D_ + (size_t)bn * D_;

    float c[4][8][4];
#pragma unroll
    for (int mt = 0; mt < 4; mt++)
#pragma unroll
        for (int nt = 0; nt < 8; nt++)
#pragma unroll
            for (int r = 0; r < 4; r++) c[mt][nt][r] = 0.0f;

    const int rowA = lane & 15;
    const int kbA  = lane >> 4;
    const int rowB = (lane & 7) + ((lane >> 4) << 3);
    const int kbB  = (lane >> 3) & 1;
    const uint32_t aoff = (uint32_t)(wm * 64 + rowA) * GM_ROWB + kbA * 16;
    const uint32_t boff = (uint32_t)(wn * 64 + rowB) * GM_ROWB + kbB * 16;

    gm_load_stage(sb, a_hi, a_lo, b_hi, b_lo, 0, tid);
    cp_commit();
    gm_load_stage(sb + GM_STAGE, a_hi, a_lo, b_hi, b_lo, 32, tid);
    cp_commit();

    int stage = 0;
    for (int i = 0; i < GM_CHUNKS; i++) {
        if (i < GM_CHUNKS - 1) cp_wait<1>(); else cp_wait<0>();
        __syncthreads();
        if (i + 2 < GM_CHUNKS) {
            int ns = (stage + 2 >= 3) ? stage - 1 : stage + 2;
            gm_load_stage(sb + ns * GM_STAGE, a_hi, a_lo, b_hi, b_lo, (i + 2) * 32, tid);
            cp_commit();
        }
        uint32_t st = sb + stage * GM_STAGE;

#pragma unroll
        for (int ks = 0; ks < 2; ks++) {
            uint32_t koff = ks * 32;
            uint32_t fah[4][4], fal[4][4];
#pragma unroll
            for (int mt = 0; mt < 4; mt++) {
                ldsm_x4(fah[mt], st + aoff + koff + mt * 16 * GM_ROWB);
                ldsm_x4(fal[mt], st + GM_A_ARR + aoff + koff + mt * 16 * GM_ROWB);
            }
#pragma unroll
            for (int np = 0; np < 4; np++) {
                uint32_t fbh[4], fbl[4];
                ldsm_x4(fbh, st + 2 * GM_A_ARR + boff + koff + np * 16 * GM_ROWB);
                ldsm_x4(fbl, st + 2 * GM_A_ARR + GM_B_ARR + boff + koff + np * 16 * GM_ROWB);
#pragma unroll
                for (int mt = 0; mt < 4; mt++) {
#pragma unroll
                    for (int half = 0; half < 2; half++) {
                        float* cc = c[mt][np * 2 + half];
                        mma_bf16(cc, fah[mt], fbh + half * 2);
                        mma_bf16(cc, fal[mt], fbh + half * 2);
                        mma_bf16(cc, fah[mt], fbl + half * 2);
                    }
                }
            }
        }
        stage = (stage + 1 >= 3) ? 0 : stage + 1;
    }

    const int erow = bm + wm * 64 + (lane >> 2);
    const int ecol = bn + wn * 64 + (lane & 3) * 2;
#pragma unroll
    for (int mt = 0; mt < 4; mt++)
#pragma unroll
        for (int nt = 0; nt < 8; nt++) {
            int r0 = erow + mt * 16;
            int cc = ecol + (nt >> 1) * 16 + (nt & 1) * 8;
            *(float2*)&C[(size_t)r0 * D_ + cc]       = make_float2(c[mt][nt][0], c[mt][nt][1]);
            *(float2*)&C[(size_t)(r0 + 8) * D_ + cc] = make_float2(c[mt][nt][2], c[mt][nt][3]);
        }
}

// ---------------------------------------------------------------------------
// RoPE tables. Freqs via fp64 pow on 16 threads only; the 65k-entry table
// uses fp32 Cody-Waite range reduction + MUFU sin/cos (no bulk fp64).
// theta is rounded to fp32 BEFORE reduction, matching reference numerics.
// ---------------------------------------------------------------------------
__global__ void rope_freq_kernel() {
    int j = threadIdx.x;
    if (j < 16) g_freqf[j] = (float)pow(1.0 / 1024.0, (double)j / 15.0);
}

__global__ __launch_bounds__(256) void rope_tables_kernel() {
    int i = blockIdx.x * blockDim.x + threadIdx.x;
    if (i >= T_ * 32) return;
    int t = i >> 5;
    int j = i & 31;
    if (j >= 16) { g_cos[i] = 1.0f; g_sin[i] = 0.0f; return; }
    float theta = (float)t * g_freqf[j];
    // Cody-Waite: r = theta - n*2pi, 2pi = c1+c2+c3, n*c1 and n*c2 exact (n<2^9)
    const float inv2pi = 0.15915494309189535f;
    const float c1 = 6.28125f;                   // 8-bit mantissa
    const float c2 = 1.9345283508300781e-3f;     // 12-bit mantissa
    const float c3 = 7.7882876e-7f;
    float n = rintf(theta * inv2pi);
    float r = fmaf(-n, c1, theta);
    r = fmaf(-n, c2, r);
    r = fmaf(-n, c3, r);
    g_cos[i] = cosf(r);
    g_sin[i] = sinf(r);
}

// ---------------------------------------------------------------------------
// Fused per-head RMSNorm + RoPE; writes head-major bf16 hi/lo.
// Q additionally scaled by 1/sqrt(HD) = 0.125.
// ---------------------------------------------------------------------------
__global__ __launch_bounds__(256) void norm_rope_kernel() {
    int gw   = (blockIdx.x * blockDim.x + threadIdx.x) >> 5;
    int lane = threadIdx.x & 31;
    if (gw >= NTOK * H_) return;

    int token = gw >> 4;
    int h = gw & 15;
    int b = token >> 11;
    int t = token & (T_ - 1);
    size_t base = (size_t)gw * 64;
    size_t hb = (((size_t)(b * H_ + h)) * T_ + t) * HD_;

    float c = g_cos[t * 32 + lane];
    float s = g_sin[t * 32 + lane];

    {   // Q (scaled by 0.125)
        float a  = g_q[base + lane];
        float b2 = g_q[base + lane + 32];
        float ss = a * a + b2 * b2;
#pragma unroll
        for (int m = 16; m > 0; m >>= 1) ss += __shfl_xor_sync(0xffffffffu, ss, m);
        float r = rsqrtf(ss * (1.0f / 64.0f) + 1e-6f);
        a *= r; b2 *= r;
        float y1 = (a * c + b2 * s) * 0.125f;
        float y2 = (-a * s + b2 * c) * 0.125f;
        __nv_bfloat16 h1 = __float2bfloat16(y1);
        __nv_bfloat16 h2 = __float2bfloat16(y2);
        g_qhi[hb + lane]      = h1;
        g_qhi[hb + lane + 32] = h2;
        g_qlo[hb + lane]      = __float2bfloat16(y1 - __bfloat162float(h1));
        g_qlo[hb + lane + 32] = __float2bfloat16(y2 - __bfloat162float(h2));
    }
    {   // K
        float a  = g_k[base + lane];
        float b2 = g_k[base + lane + 32];
        float ss = a * a + b2 * b2;
#pragma unroll
        for (int m = 16; m > 0; m >>= 1) ss += __shfl_xor_sync(0xffffffffu, ss, m);
        float r = rsqrtf(ss * (1.0f / 64.0f) + 1e-6f);
        a *= r; b2 *= r;
        float y1 = a * c + b2 * s;
        float y2 = -a * s + b2 * c;
        __nv_bfloat16 h1 = __float2bfloat16(y1);
        __nv_bfloat16 h2 = __float2bfloat16(y2);
        g_khi[hb + lane]      = h1;
        g_khi[hb + lane + 32] = h2;
        g_klo[hb + lane]      = __float2bfloat16(y1 - __bfloat162float(h1));
        g_klo[hb + lane + 32] = __float2bfloat16(y2 - __bfloat162float(h2));
    }
}

// ---------------------------------------------------------------------------
// Flash attention via mma.sync, bf16x3 (causal). 128-query x 128-key tiles.
// 8 warps each own 16 query rows. SMEM rows padded to 144B.
// ---------------------------------------------------------------------------
#define FROWB   144u
#define FQ_SIZE (128 * 144)          // 18432 per Q array (hi/lo)
#define FKV_OFF (2 * FQ_SIZE)        // 36864
#define FKV_ARR (128 * 144)          // 18432
#define FSTAGE  (4 * FKV_ARR)        // 73728: khi, klo, vhi, vlo
#define FMMA_SMEM (FKV_OFF + 2 * FSTAGE)   // 184320

__device__ __forceinline__ void f_load_kv(
    uint32_t dst, const __nv_bfloat16* kh, const __nv_bfloat16* kl,
    const __nv_bfloat16* vh, const __nv_bfloat16* vl, size_t goff, int tid)
{
    const __nv_bfloat16* srcs[4] = {kh, kl, vh, vl};
    int seg = tid & 7, r0 = tid >> 3;
#pragma unroll
    for (int arr = 0; arr < 4; arr++) {
        const __nv_bfloat16* s = srcs[arr] + goff + seg * 8;
        uint32_t d = dst + arr * FKV_ARR + seg * 16;
#pragma unroll
        for (int rr = 0; rr < 4; rr++) {
            int row = r0 + rr * 32;
            cp_async16(d + row * FROWB, s + row * HD_);
        }
    }
}

__global__ __launch_bounds__(256, 1) void flash_mma_kernel(
    const __nv_bfloat16* __restrict__ Qhi, const __nv_bfloat16* __restrict__ Qlo,
    const __nv_bfloat16* __restrict__ Khi, const __nv_bfloat16* __restrict__ Klo,
    const __nv_bfloat16* __restrict__ Vhi, const __nv_bfloat16* __restrict__ Vlo,
    float* __restrict__ O)
{
    extern __shared__ __align__(128) char fsm[];
    uint32_t sb = smem_to_u32(fsm);
    const int tid = threadIdx.x, wid = tid >> 5, lane = tid & 31;
    const int bh = blockIdx.x;
    const int qt = 15 - blockIdx.y;          // big tiles first
    const int b = bh >> 4, h = bh & 15;
    const size_t headoff = (size_t)bh * T_ * HD_;
    const int nkt = qt + 1;                  // 128-key tiles

    // prologue: Q(hi+lo) + KV stage 0 in one group
    {
        int seg = tid & 7, r0 = tid >> 3;
        const __nv_bfloat16* q0 = Qhi + headoff + (size_t)qt * 128 * HD_ + seg * 8;
        const __nv_bfloat16* q1 = Qlo + headoff + (size_t)qt * 128 * HD_ + seg * 8;
#pragma unroll
        for (int rr = 0; rr < 4; rr++) {
            int row = r0 + rr * 32;
            cp_async16(sb + row * FROWB + seg * 16, q0 + row * HD_);
            cp_async16(sb + FQ_SIZE + row * FROWB + seg * 16, q1 + row * HD_);
        }
    }
    f_load_kv(sb + FKV_OFF, Khi, Klo, Vhi, Vlo, headoff, tid);
    cp_commit();

    uint32_t fqh[4][4], fql[4][4];
    float o[8][4];
#pragma unroll
    for (int nt = 0; nt < 8; nt++)
#pragma unroll
        for (int r = 0; r < 4; r++) o[nt][r] = 0.0f;
    float m0 = -1e30f, m1 = -1e30f, l0 = 0.0f, l1 = 0.0f;

    const uint32_t qrow_off = (uint32_t)(wid * 16 + (lane & 15)) * FROWB + (lane >> 4) * 16;
    const uint32_t krow_off = (uint32_t)((lane & 7) + ((lane >> 4) << 3)) * FROWB
                              + ((lane >> 3) & 1) * 16;
    const uint32_t vrow_off = (uint32_t)(lane & 15) * FROWB + (lane >> 4) * 16;

    for (int jt = 0; jt < nkt; jt++) {
        if (jt + 1 < nkt) {
            f_load_kv(sb + FKV_OFF + ((jt + 1) & 1) * FSTAGE, Khi, Klo, Vhi, Vlo,
                      headoff + (size_t)(jt + 1) * 128 * HD_, tid);
            cp_commit();
            cp_wait<1>();
        } else {
            cp_wait<0>();
        }
        __syncthreads();

        if (jt == 0) {
#pragma unroll
            for (int ks = 0; ks < 4; ks++) {
                ldsm_x4(fqh[ks], sb + qrow_off + ks * 32);
                ldsm_x4(fql[ks], sb + FQ_SIZE + qrow_off + ks * 32);
            }
        }

        uint32_t st = sb + FKV_OFF + (jt & 1) * FSTAGE;

        // S = Q K^T over 128 keys
        float s[16][4];
#pragma unroll
        for (int nt = 0; nt < 16; nt++)
#pragma unroll
            for (int r = 0; r < 4; r++) s[nt][r] = 0.0f;

#pragma unroll
        for (int np = 0; np < 8; np++) {
#pragma unroll
            for (int ks = 0; ks < 4; ks++) {
                uint32_t addr = st + krow_off + np * 16 * FROWB + ks * 32;
                uint32_t fk[4];
                ldsm_x4(fk, addr);
                mma_bf16(s[2 * np],     fqh[ks], fk + 0);
                mma_bf16(s[2 * np + 1], fqh[ks], fk + 2);
                mma_bf16(s[2 * np],     fql[ks], fk + 0);
                mma_bf16(s[2 * np + 1], fql[ks], fk + 2);
                ldsm_x4(fk, addr + FKV_ARR);
                mma_bf16(s[2 * np],     fqh[ks], fk + 0);
                mma_bf16(s[2 * np + 1], fqh[ks], fk + 2);
            }
        }

        // causal mask: only the last (diagonal) tile
        if (jt == qt) {
            int grow = qt * 128 + wid * 16 + (lane >> 2);
            int gc0 = jt * 128 + (lane & 3) * 2;
#pragma unroll
            for (int nt = 0; nt < 16; nt++) {
                int cc = gc0 + nt * 8;
                if (cc > grow)          s[nt][0] = -1e30f;
                if (cc + 1 > grow)      s[nt][1] = -1e30f;
                if (cc > grow + 8)      s[nt][2] = -1e30f;
                if (cc + 1 > grow + 8)  s[nt][3] = -1e30f;
            }
        }

        // online softmax
        float mx0 = -1e30f, mx1 = -1e30f;
#pragma unroll
        for (int nt = 0; nt < 16; nt++) {
            mx0 = fmaxf(mx0, fmaxf(s[nt][0], s[nt][1]));
            mx1 = fmaxf(mx1, fmaxf(s[nt][2], s[nt][3]));
        }
        mx0 = fmaxf(mx0, __shfl_xor_sync(0xffffffffu, mx0, 1));
        mx0 = fmaxf(mx0, __shfl_xor_sync(0xffffffffu, mx0, 2));
        mx1 = fmaxf(mx1, __shfl_xor_sync(0xffffffffu, mx1, 1));
        mx1 = fmaxf(mx1, __shfl_xor_sync(0xffffffffu, mx1, 2));
        float mn0 = fmaxf(m0, mx0), mn1 = fmaxf(m1, mx1);
        float al0 = __expf(m0 - mn0), al1 = __expf(m1 - mn1);
        float rs0 = 0.0f, rs1 = 0.0f;
#pragma unroll
        for (int nt = 0; nt < 16; nt++) {
            s[nt][0] = __expf(s[nt][0] - mn0);
            s[nt][1] = __expf(s[nt][1] - mn0);
            s[nt][2] = __expf(s[nt][2] - mn1);
            s[nt][3] = __expf(s[nt][3] - mn1);
            rs0 += s[nt][0] + s[nt][1];
            rs1 += s[nt][2] + s[nt][3];
        }
        rs0 += __shfl_xor_sync(0xffffffffu, rs0, 1);
        rs0 += __shfl_xor_sync(0xffffffffu, rs0, 2);
        rs1 += __shfl_xor_sync(0xffffffffu, rs1, 1);
        rs1 += __shfl_xor_sync(0xffffffffu, rs1, 2);
        l0 = l0 * al0 + rs0; m0 = mn0;
        l1 = l1 * al1 + rs1; m1 = mn1;
#pragma unroll
        for (int nt = 0; nt < 8; nt++) {
            o[nt][0] *= al0; o[nt][1] *= al0;
            o[nt][2] *= al1; o[nt][3] *= al1;
        }

        // P -> bf16 hi/lo A-fragments (8 k-steps of 16 keys)
        uint32_t fph[8][4], fpl[8][4];
#pragma unroll
        for (int f = 0; f < 8; f++) {
#pragma unroll
            for (int half = 0; half < 2; half++) {
                int nt = 2 * f + half;
#pragma unroll
                for (int rh = 0; rh < 2; rh++) {
                    float p0 = s[nt][rh * 2], p1 = s[nt][rh * 2 + 1];
                    uint32_t hi = pack_bf16x2(p0, p1);
                    float h0 = __uint_as_float(hi << 16);
                    float h1 = __uint_as_float(hi & 0xFFFF0000u);
                    uint32_t lo = pack_bf16x2(p0 - h0, p1 - h1);
                    fph[f][half * 2 + rh] = hi;
                    fpl[f][half * 2 + rh] = lo;
                }
            }
        }

        // O += P V over 128 keys
#pragma unroll
        for (int nh = 0; nh < 4; nh++) {
#pragma unroll
            for (int ks = 0; ks < 8; ks++) {
                uint32_t addr = st + 2 * FKV_ARR + vrow_off + ks * 16 * FROWB + nh * 32;
                uint32_t fv[4];
                ldsm_x4_t(fv, addr);
                mma_bf16(o[2 * nh],     fph[ks], fv + 0);
                mma_bf16(o[2 * nh + 1], fph[ks], fv + 2);
                mma_bf16(o[2 * nh],     fpl[ks], fv + 0);
                mma_bf16(o[2 * nh + 1], fpl[ks], fv + 2);
                ldsm_x4_t(fv, addr + FKV_ARR);
                mma_bf16(o[2 * nh],     fph[ks], fv + 0);
                mma_bf16(o[2 * nh + 1], fph[ks], fv + 2);
            }
        }
        __syncthreads();
    }

    float inv0 = 1.0f / l0, inv1 = 1.0f / l1;
    int row = qt * 128 + wid * 16 + (lane >> 2);
    float* op0 = O + ((size_t)b * T_ + row) * D_ + h * 64 + (lane & 3) * 2;
    float* op1 = op0 + 8 * D_;
#pragma unroll
    for (int nt = 0; nt < 8; nt++) {
        *(float2*)(op0 + nt * 8) = make_float2(o[nt][0] * inv0, o[nt][1] * inv0);
        *(float2*)(op1 + nt * 8) = make_float2(o[nt][2] * inv1, o[nt][3] * inv1);
    }
}

// ---------------------------------------------------------------------------
// Launch
// ---------------------------------------------------------------------------
extern "C" void kernel_launch(void* const* d_in, const int* in_sizes, int n_in,
                              void* d_out, int out_size)
{
    (void)in_sizes; (void)n_in; (void)out_size;
    const float* x  = (const float*)d_in[0];
    const float* w[4] = {(const float*)d_in[1], (const float*)d_in[2],
                         (const float*)d_in[3], (const float*)d_in[4]};
    float* out = (float*)d_out;

    float *qp, *kp, *vp, *op;
    __nv_bfloat16 *ahi, *alo, *whi, *wlo;
    __nv_bfloat16 *qhi, *qlo, *khi, *klo, *vhi, *vlo;
    cudaGetSymbolAddress((void**)&qp, g_q);
    cudaGetSymbolAddress((void**)&kp, g_k);
    cudaGetSymbolAddress((void**)&vp, g_v);
    cudaGetSymbolAddress((void**)&op, g_o);
    cudaGetSymbolAddress((void**)&ahi, g_ahi);
    cudaGetSymbolAddress((void**)&alo, g_alo);
    cudaGetSymbolAddress((void**)&whi, g_whi);
    cudaGetSymbolAddress((void**)&wlo, g_wlo);
    cudaGetSymbolAddress((void**)&qhi, g_qhi);
    cudaGetSymbolAddress((void**)&qlo, g_qlo);
    cudaGetSymbolAddress((void**)&khi, g_khi);
    cudaGetSymbolAddress((void**)&klo, g_klo);
    cudaGetSymbolAddress((void**)&vhi, g_vhi);
    cudaGetSymbolAddress((void**)&vlo, g_vlo);

    cudaFuncSetAttribute(gemm_mma_kernel,
                         cudaFuncAttributeMaxDynamicSharedMemorySize, GM_SMEM);
    cudaFuncSetAttribute(flash_mma_kernel,
                         cudaFuncAttributeMaxDynamicSharedMemorySize, FMMA_SMEM);

    rope_freq_kernel<<<1, 16>>>();
    rope_tables_kernel<<<(T_ * 32 + 255) / 256, 256>>>();

    split_kernel<<<(NTOK * D_ / 4 + 255) / 256, 256>>>(x, ahi, alo, NTOK * D_);
    split_w_kernel<<<(4 * D_ * D_ / 4 + 255) / 256, 256>>>(
        w[0], w[1], w[2], w[3], whi, wlo);

    gemm_mma_kernel<<<dim3(D_ / 128, NTOK / 256, 3), 256, GM_SMEM>>>(
        ahi, alo, whi, wlo, 0, qp, kp, vp);

    norm_rope_kernel<<<(NTOK * H_) / 8, 256>>>();
    split_v_kernel<<<(NTOK * D_ / 4 + 255) / 256, 256>>>();

    flash_mma_kernel<<<dim3(BH_, T_ / 128), 256, FMMA_SMEM>>>(
        qhi, qlo, khi, klo, vhi, vlo, op);

    split_kernel<<<(NTOK * D_ / 4 + 255) / 256, 256>>>(op, ahi, alo, NTOK * D_);
    gemm_mma_kernel<<<dim3(D_ / 128, NTOK / 256, 1), 256, GM_SMEM>>>(
        ahi, alo, whi, wlo, 3, out, out, out);
}